// round 14
// baseline (speedup 1.0000x reference)
#include <cuda_runtime.h>
#include <cstdint>

#define B_    4
#define H_    8
#define TK_   512
#define NK_   511
#define L_    1023
#define D_    512
#define HD_   64
#define BH_   32
#define ROWS_ 4092          // B_*L_

// Scratch (static __device__ — no allocations allowed)
__device__ float    g_q [B_*H_*L_*HD_];
__device__ uint32_t g_kh[B_*H_*L_*HD_];   // K pre-split tf32 hi
__device__ uint32_t g_kl[B_*H_*L_*HD_];   // K pre-split tf32 lo
__device__ uint32_t g_vh[B_*H_*L_*HD_];   // V pre-split tf32 hi
__device__ uint32_t g_vl[B_*H_*L_*HD_];   // V pre-split tf32 lo
__device__ float    g_ao[B_*L_*D_];       // attention output, (B,L, H*HD)

// ---------------------------------------------------------------------------
// tf32 helpers
// ---------------------------------------------------------------------------
__device__ __forceinline__ void split_tf32(float x, uint32_t& hi, uint32_t& lo)
{
    float h, l2;
    asm("cvt.rna.tf32.f32 %0, %1;" : "=f"(h) : "f"(x));
    float l = x - h;
    asm("cvt.rna.tf32.f32 %0, %1;" : "=f"(l2) : "f"(l));
    hi = __float_as_uint(h);
    lo = __float_as_uint(l2);
}

#define MMA_TF32(d, a, b)                                                     \
    asm volatile(                                                             \
        "mma.sync.aligned.m16n8k8.row.col.f32.tf32.tf32.f32 "                 \
        "{%0,%1,%2,%3}, {%4,%5,%6,%7}, {%8,%9}, {%0,%1,%2,%3};"               \
        : "+f"((d)[0]), "+f"((d)[1]), "+f"((d)[2]), "+f"((d)[3])              \
        : "r"((a)[0]), "r"((a)[1]), "r"((a)[2]), "r"((a)[3]),                 \
          "r"((b)[0]), "r"((b)[1]))

// ldmatrix x4: 4 8x8 b16 matrices; register layout == tf32 mma fragment.
#define LDSM_X4(R0, R1, R2, R3, ADDR)                                         \
    asm volatile("ldmatrix.sync.aligned.m8n8.x4.shared.b16 {%0,%1,%2,%3}, [%4];" \
        : "=r"(R0), "=r"(R1), "=r"(R2), "=r"(R3) : "r"(ADDR))

__device__ __forceinline__ uint32_t smem_u32(const void* p)
{
    return (uint32_t)__cvta_generic_to_shared(p);
}

// GEMM kernels: k-chunk = 32 -> stride 36 (single-buffered, round-11 proven)
#define AST_ 36
#define GEMM_SMEM_BYTES ((2*128*AST_ + 2*64*AST_) * 4)   // 55296
// Flash tiles hold full k=64 -> stride 68
#define FST_ 68
#define FLASH_SMEM (6*64*FST_*4 + 2*64*4)                // 104960

// ---------------------------------------------------------------------------
// Kernel 1: fused QKV projection (round-11 LDSM mainloop; epilogue writes K/V
// pre-split so the flash kernel never re-splits them).
// ---------------------------------------------------------------------------
__global__ void __launch_bounds__(256, 2)
qkv_mma_kernel(const float* __restrict__ leaves,
               const float* __restrict__ nodes,
               const float* __restrict__ Wq,
               const float* __restrict__ Wk,
               const float* __restrict__ Wv,
               const float* __restrict__ bq,
               const float* __restrict__ bk,
               const float* __restrict__ bv)
{
    const int z = blockIdx.z;
    const float* W    = (z == 0) ? Wq : (z == 1) ? Wk : Wv;
    const float* bias = (z == 0) ? bq : (z == 1) ? bk : bv;
    const float scale = (z == 0) ? 0.125f : 1.0f;

    extern __shared__ uint32_t smem_u[];
    uint32_t* AH = smem_u;
    uint32_t* AL = AH + 128 * AST_;
    uint32_t* BH = AL + 128 * AST_;
    uint32_t* BL = BH + 64 * AST_;

    const int tid  = threadIdx.x;
    const int warp = tid >> 5;
    const int lane = tid & 31;
    const int g    = lane >> 2;
    const int tig  = lane & 3;
    const int warpM = warp & 3;
    const int warpN = warp >> 2;
    const int M0 = warpM * 32;
    const int N0 = warpN * 32;

    const int r0 = blockIdx.y * 128;
    const int c0 = blockIdx.x * 64;

    const int lm = tid >> 3;
    const int lk = (tid & 7) * 4;

    const int r8 = lane & 7;
    const int mi = lane >> 3;
    const int rowA = (mi & 1) * 8 + r8, kA = (mi >> 1) * 4;
    const int rowB = (mi >> 1) * 8 + r8, kB = (mi & 1) * 4;
    const uint32_t ah_addr = smem_u32(AH) + (((M0 + rowA) * AST_ + kA) << 2);
    const uint32_t al_addr = smem_u32(AL) + (((M0 + rowA) * AST_ + kA) << 2);
    const uint32_t bh_addr = smem_u32(BH) + (((N0 + rowB) * AST_ + kB) << 2);
    const uint32_t bl_addr = smem_u32(BL) + (((N0 + rowB) * AST_ + kB) << 2);
    const uint32_t MT_STEP = (16 * AST_) << 2;

    const float* xsrc[4];
    #pragma unroll
    for (int p = 0; p < 4; p++) {
        int gr = r0 + lm + p * 32;
        if (gr < ROWS_) {
            int b = gr / L_, t = gr % L_;
            xsrc[p] = (t < TK_) ? (leaves + ((size_t)(b * TK_ + t)) * D_)
                                : (nodes  + ((size_t)(b * NK_ + (t - TK_))) * D_);
        } else xsrc[p] = nullptr;
    }
    const float* wsrc0 = W + (size_t)(c0 + lm) * D_;
    const float* wsrc1 = W + (size_t)(c0 + lm + 32) * D_;

    float acc[2][4][4] = {};

    float4 xa[4], wb[2];
    #pragma unroll
    for (int p = 0; p < 4; p++) {
        xa[p] = make_float4(0.f, 0.f, 0.f, 0.f);
        if (xsrc[p]) xa[p] = *reinterpret_cast<const float4*>(xsrc[p] + lk);
    }
    wb[0] = *reinterpret_cast<const float4*>(wsrc0 + lk);
    wb[1] = *reinterpret_cast<const float4*>(wsrc1 + lk);

    for (int k0 = 0; k0 < D_; k0 += 32) {
        __syncthreads();
        #pragma unroll
        for (int p = 0; p < 4; p++) {
            uint4 h4, l4;
            split_tf32(xa[p].x, h4.x, l4.x);
            split_tf32(xa[p].y, h4.y, l4.y);
            split_tf32(xa[p].z, h4.z, l4.z);
            split_tf32(xa[p].w, h4.w, l4.w);
            int m = lm + p * 32;
            *reinterpret_cast<uint4*>(AH + m * AST_ + lk) = h4;
            *reinterpret_cast<uint4*>(AL + m * AST_ + lk) = l4;
        }
        #pragma unroll
        for (int p = 0; p < 2; p++) {
            uint4 h4, l4;
            split_tf32(wb[p].x, h4.x, l4.x);
            split_tf32(wb[p].y, h4.y, l4.y);
            split_tf32(wb[p].z, h4.z, l4.z);
            split_tf32(wb[p].w, h4.w, l4.w);
            int n = lm + p * 32;
            *reinterpret_cast<uint4*>(BH + n * AST_ + lk) = h4;
            *reinterpret_cast<uint4*>(BL + n * AST_ + lk) = l4;
        }
        __syncthreads();

        if (k0 + 32 < D_) {
            #pragma unroll
            for (int p = 0; p < 4; p++) {
                if (xsrc[p]) xa[p] = *reinterpret_cast<const float4*>(xsrc[p] + k0 + 32 + lk);
            }
            wb[0] = *reinterpret_cast<const float4*>(wsrc0 + k0 + 32 + lk);
            wb[1] = *reinterpret_cast<const float4*>(wsrc1 + k0 + 32 + lk);
        }

        #pragma unroll
        for (int ks = 0; ks < 4; ks++) {
            const uint32_t koff = (ks * 8) << 2;
            uint32_t ah[2][4], al[2][4], bh[4][2], bl[4][2];
            LDSM_X4(ah[0][0], ah[0][1], ah[0][2], ah[0][3], ah_addr + koff);
            LDSM_X4(ah[1][0], ah[1][1], ah[1][2], ah[1][3], ah_addr + MT_STEP + koff);
            LDSM_X4(al[0][0], al[0][1], al[0][2], al[0][3], al_addr + koff);
            LDSM_X4(al[1][0], al[1][1], al[1][2], al[1][3], al_addr + MT_STEP + koff);
            uint32_t t0, t1, t2, t3;
            LDSM_X4(t0, t1, t2, t3, bh_addr + koff);
            bh[0][0] = t0; bh[0][1] = t1; bh[1][0] = t2; bh[1][1] = t3;
            LDSM_X4(t0, t1, t2, t3, bh_addr + MT_STEP + koff);
            bh[2][0] = t0; bh[2][1] = t1; bh[3][0] = t2; bh[3][1] = t3;
            LDSM_X4(t0, t1, t2, t3, bl_addr + koff);
            bl[0][0] = t0; bl[0][1] = t1; bl[1][0] = t2; bl[1][1] = t3;
            LDSM_X4(t0, t1, t2, t3, bl_addr + MT_STEP + koff);
            bl[2][0] = t0; bl[2][1] = t1; bl[3][0] = t2; bl[3][1] = t3;

            #pragma unroll
            for (int mt = 0; mt < 2; mt++)
                #pragma unroll
                for (int nt = 0; nt < 4; nt++) {
                    MMA_TF32(acc[mt][nt], ah[mt], bh[nt]);
                    MMA_TF32(acc[mt][nt], ah[mt], bl[nt]);
                    MMA_TF32(acc[mt][nt], al[mt], bh[nt]);
                }
        }
    }

    // ---- epilogue: q as f32; k/v written pre-split (proven in round 8) ----
    #pragma unroll
    for (int mt = 0; mt < 2; mt++)
        #pragma unroll
        for (int nt = 0; nt < 4; nt++) {
            int col = N0 + nt * 8 + tig * 2;
            int gc = c0 + col;
            int hd = gc >> 6, d = gc & 63;
            float b0v = bias[gc], b1v = bias[gc + 1];
            #pragma unroll
            for (int hh = 0; hh < 2; hh++) {
                int gr = r0 + M0 + mt * 16 + g + hh * 8;
                if (gr >= ROWS_) continue;
                int b = gr / L_, l = gr % L_;
                float v0 = (acc[mt][nt][hh * 2 + 0] + b0v) * scale;
                float v1 = (acc[mt][nt][hh * 2 + 1] + b1v) * scale;
                size_t o = (((size_t)(b * H_ + hd)) * L_ + l) * HD_ + d;
                if (z == 0) {
                    g_q[o] = v0;
                    g_q[o + 1] = v1;
                } else {
                    uint32_t h0, l0, h1, l1;
                    split_tf32(v0, h0, l0);
                    split_tf32(v1, h1, l1);
                    uint32_t* dh = (z == 1) ? g_kh : g_vh;
                    uint32_t* dl = (z == 1) ? g_kl : g_vl;
                    dh[o] = h0; dh[o + 1] = h1;
                    dl[o] = l0; dl[o + 1] = l1;
                }
            }
        }
}

// ---------------------------------------------------------------------------
// Kernel 3: out = g_ao @ Wo^T + bo  (round-11 verbatim, ldmatrix)
// ---------------------------------------------------------------------------
__global__ void __launch_bounds__(256, 2)
oproj_mma_kernel(const float* __restrict__ Wo,
                 const float* __restrict__ bo,
                 float* __restrict__ out)
{
    extern __shared__ uint32_t smem_u[];
    uint32_t* AH = smem_u;
    uint32_t* AL = AH + 128 * AST_;
    uint32_t* BH = AL + 128 * AST_;
    uint32_t* BL = BH + 64 * AST_;

    const int tid  = threadIdx.x;
    const int warp = tid >> 5;
    const int lane = tid & 31;
    const int g    = lane >> 2;
    const int tig  = lane & 3;
    const int warpM = warp & 3;
    const int warpN = warp >> 2;
    const int M0 = warpM * 32;
    const int N0 = warpN * 32;

    const int r0 = blockIdx.y * 128;
    const int c0 = blockIdx.x * 64;

    const int lm = tid >> 3;
    const int lk = (tid & 7) * 4;

    const int r8 = lane & 7;
    const int mi = lane >> 3;
    const int rowA = (mi & 1) * 8 + r8, kA = (mi >> 1) * 4;
    const int rowB = (mi >> 1) * 8 + r8, kB = (mi & 1) * 4;
    const uint32_t ah_addr = smem_u32(AH) + (((M0 + rowA) * AST_ + kA) << 2);
    const uint32_t al_addr = smem_u32(AL) + (((M0 + rowA) * AST_ + kA) << 2);
    const uint32_t bh_addr = smem_u32(BH) + (((N0 + rowB) * AST_ + kB) << 2);
    const uint32_t bl_addr = smem_u32(BL) + (((N0 + rowB) * AST_ + kB) << 2);
    const uint32_t MT_STEP = (16 * AST_) << 2;

    const float* xsrc[4];
    #pragma unroll
    for (int p = 0; p < 4; p++) {
        int gr = r0 + lm + p * 32;
        xsrc[p] = (gr < ROWS_) ? (g_ao + (size_t)gr * D_) : nullptr;
    }
    const float* wsrc0 = Wo + (size_t)(c0 + lm) * D_;
    const float* wsrc1 = Wo + (size_t)(c0 + lm + 32) * D_;

    float acc[2][4][4] = {};

    float4 xa[4], wb[2];
    #pragma unroll
    for (int p = 0; p < 4; p++) {
        xa[p] = make_float4(0.f, 0.f, 0.f, 0.f);
        if (xsrc[p]) xa[p] = *reinterpret_cast<const float4*>(xsrc[p] + lk);
    }
    wb[0] = *reinterpret_cast<const float4*>(wsrc0 + lk);
    wb[1] = *reinterpret_cast<const float4*>(wsrc1 + lk);

    for (int k0 = 0; k0 < D_; k0 += 32) {
        __syncthreads();
        #pragma unroll
        for (int p = 0; p < 4; p++) {
            uint4 h4, l4;
            split_tf32(xa[p].x, h4.x, l4.x);
            split_tf32(xa[p].y, h4.y, l4.y);
            split_tf32(xa[p].z, h4.z, l4.z);
            split_tf32(xa[p].w, h4.w, l4.w);
            int m = lm + p * 32;
            *reinterpret_cast<uint4*>(AH + m * AST_ + lk) = h4;
            *reinterpret_cast<uint4*>(AL + m * AST_ + lk) = l4;
        }
        #pragma unroll
        for (int p = 0; p < 2; p++) {
            uint4 h4, l4;
            split_tf32(wb[p].x, h4.x, l4.x);
            split_tf32(wb[p].y, h4.y, l4.y);
            split_tf32(wb[p].z, h4.z, l4.z);
            split_tf32(wb[p].w, h4.w, l4.w);
            int n = lm + p * 32;
            *reinterpret_cast<uint4*>(BH + n * AST_ + lk) = h4;
            *reinterpret_cast<uint4*>(BL + n * AST_ + lk) = l4;
        }
        __syncthreads();

        if (k0 + 32 < D_) {
            #pragma unroll
            for (int p = 0; p < 4; p++) {
                if (xsrc[p]) xa[p] = *reinterpret_cast<const float4*>(xsrc[p] + k0 + 32 + lk);
            }
            wb[0] = *reinterpret_cast<const float4*>(wsrc0 + k0 + 32 + lk);
            wb[1] = *reinterpret_cast<const float4*>(wsrc1 + k0 + 32 + lk);
        }

        #pragma unroll
        for (int ks = 0; ks < 4; ks++) {
            const uint32_t koff = (ks * 8) << 2;
            uint32_t ah[2][4], al[2][4], bh[4][2], bl[4][2];
            LDSM_X4(ah[0][0], ah[0][1], ah[0][2], ah[0][3], ah_addr + koff);
            LDSM_X4(ah[1][0], ah[1][1], ah[1][2], ah[1][3], ah_addr + MT_STEP + koff);
            LDSM_X4(al[0][0], al[0][1], al[0][2], al[0][3], al_addr + koff);
            LDSM_X4(al[1][0], al[1][1], al[1][2], al[1][3], al_addr + MT_STEP + koff);
            uint32_t t0, t1, t2, t3;
            LDSM_X4(t0, t1, t2, t3, bh_addr + koff);
            bh[0][0] = t0; bh[0][1] = t1; bh[1][0] = t2; bh[1][1] = t3;
            LDSM_X4(t0, t1, t2, t3, bh_addr + MT_STEP + koff);
            bh[2][0] = t0; bh[2][1] = t1; bh[3][0] = t2; bh[3][1] = t3;
            LDSM_X4(t0, t1, t2, t3, bl_addr + koff);
            bl[0][0] = t0; bl[0][1] = t1; bl[1][0] = t2; bl[1][1] = t3;
            LDSM_X4(t0, t1, t2, t3, bl_addr + MT_STEP + koff);
            bl[2][0] = t0; bl[2][1] = t1; bl[3][0] = t2; bl[3][1] = t3;

            #pragma unroll
            for (int mt = 0; mt < 2; mt++)
                #pragma unroll
                for (int nt = 0; nt < 4; nt++) {
                    MMA_TF32(acc[mt][nt], ah[mt], bh[nt]);
                    MMA_TF32(acc[mt][nt], ah[mt], bl[nt]);
                    MMA_TF32(acc[mt][nt], al[mt], bh[nt]);
                }
        }
    }

    #pragma unroll
    for (int mt = 0; mt < 2; mt++)
        #pragma unroll
        for (int nt = 0; nt < 4; nt++) {
            int gc = c0 + N0 + nt * 8 + tig * 2;
            float b0v = bo[gc], b1v = bo[gc + 1];
            #pragma unroll
            for (int hh = 0; hh < 2; hh++) {
                int gr = r0 + M0 + mt * 16 + g + hh * 8;
                if (gr >= ROWS_) continue;
                float* dst = out + (size_t)gr * D_ + gc;
                dst[0] = acc[mt][nt][hh * 2 + 0] + b0v;
                dst[1] = acc[mt][nt][hh * 2 + 1] + b1v;
            }
        }
}

// ---------------------------------------------------------------------------
// Kernel 2: flash attention — round-7 structure; K/V arrive PRE-SPLIT so the
// tile load is a pure uint4 copy (both pieces proven correct in round 8).
// ---------------------------------------------------------------------------
__global__ void flash_mma_kernel(const int* __restrict__ node_indices,
                                 const unsigned char* __restrict__ key_pad,
                                 const unsigned char* __restrict__ node_pad)
{
    extern __shared__ uint32_t sm[];
    uint32_t* KH = sm;
    uint32_t* KL = KH + 64 * FST_;
    uint32_t* VH = KL + 64 * FST_;
    uint32_t* VL = VH + 64 * FST_;
    uint32_t* PH = VL + 64 * FST_;
    uint32_t* PL = PH + 64 * FST_;
    int* clo = (int*)(PL + 64 * FST_);
    int* chi = clo + 64;

    const int bh = blockIdx.y;
    const int b  = bh >> 3;
    const int h  = bh & 7;
    const int i0 = blockIdx.x * 64;
    const bool qleaf = (i0 < TK_);

    const int tid  = threadIdx.x;       // 128
    const int warp = tid >> 5;
    const int lane = tid & 31;
    const int g    = lane >> 2;
    const int tig  = lane & 3;
    const int wrow = warp * 16;

    const int lj = tid >> 4;            // 0..7
    const int lc = (tid & 15) * 4;      // 0,4,...,60

    #pragma unroll
    for (int p = 0; p < 8; p++) {
        int row = p * 8 + lj;
        int gi = i0 + row;
        float4 qv = make_float4(0.f, 0.f, 0.f, 0.f);
        if (gi < L_)
            qv = *reinterpret_cast<const float4*>(g_q + ((size_t)bh * L_ + gi) * HD_ + lc);
        uint4 h4, l4;
        split_tf32(qv.x, h4.x, l4.x);
        split_tf32(qv.y, h4.y, l4.y);
        split_tf32(qv.z, h4.z, l4.z);
        split_tf32(qv.w, h4.w, l4.w);
        *reinterpret_cast<uint4*>(PH + row * FST_ + lc) = h4;
        *reinterpret_cast<uint4*>(PL + row * FST_ + lc) = l4;
    }
    __syncthreads();

    uint32_t qh[8][4], ql[8][4];
    #pragma unroll
    for (int kk = 0; kk < 8; kk++) {
        int base0 = (wrow + g) * FST_ + kk * 8;
        int base1 = (wrow + 8 + g) * FST_ + kk * 8;
        qh[kk][0] = PH[base0 + tig];
        qh[kk][1] = PH[base1 + tig];
        qh[kk][2] = PH[base0 + tig + 4];
        qh[kk][3] = PH[base1 + tig + 4];
        ql[kk][0] = PL[base0 + tig];
        ql[kk][1] = PL[base1 + tig];
        ql[kk][2] = PL[base0 + tig + 4];
        ql[kk][3] = PL[base1 + tig + 4];
    }

    const int r0 = i0 + wrow + g;
    const int r1 = r0 + 8;
    int qlo0 = 0, qhi0 = 0, qloL0 = 0, qlo1 = 0, qhi1 = 0, qloL1 = 0;
    if (!qleaf) {
        int nq0 = min(r0 - TK_, NK_ - 1);
        qlo0 = node_indices[((size_t)bh * NK_ + nq0) * 2 + 0];
        qhi0 = node_indices[((size_t)bh * NK_ + nq0) * 2 + 1];
        qloL0 = (node_pad[b * NK_ + nq0] != 0) ? (1 << 28) : qlo0;
        int nq1 = min(r1 - TK_, NK_ - 1);
        qlo1 = node_indices[((size_t)bh * NK_ + nq1) * 2 + 0];
        qhi1 = node_indices[((size_t)bh * NK_ + nq1) * 2 + 1];
        qloL1 = (node_pad[b * NK_ + nq1] != 0) ? (1 << 28) : qlo1;
    }

    float m0 = -1e30f, m1 = -1e30f, lsum0 = 0.f, lsum1 = 0.f;
    float acc[8][4] = {};

    const int ntiles = qleaf ? 8 : (9 + (i0 - TK_) / 64);
    for (int jt = 0; jt < ntiles; jt++) {
        const bool nodetile = (jt >= 8);
        const int j0 = nodetile ? TK_ + (jt - 8) * 64 : jt * 64;

        __syncthreads();
        // ---- K tile: pure uint4 copy of pre-split data ----
        #pragma unroll
        for (int p = 0; p < 8; p++) {
            int row = p * 8 + lj;
            int gj = j0 + row;
            uint4 h4 = make_uint4(0, 0, 0, 0), l4 = make_uint4(0, 0, 0, 0);
            if (gj < L_) {
                size_t o = ((size_t)bh * L_ + gj) * HD_ + lc;
                h4 = *reinterpret_cast<const uint4*>(g_kh + o);
                l4 = *reinterpret_cast<const uint4*>(g_kl + o);
            }
            *reinterpret_cast<uint4*>(KH + row * FST_ + lc) = h4;
            *reinterpret_cast<uint4*>(KL + row * FST_ + lc) = l4;
        }
        // ---- V tile: pure uint4 copy of pre-split data ----
        #pragma unroll
        for (int p = 0; p < 8; p++) {
            int row = p * 8 + lj;
            int gj = j0 + row;
            uint4 h4 = make_uint4(0, 0, 0, 0), l4 = make_uint4(0, 0, 0, 0);
            if (gj < L_) {
                size_t o = ((size_t)bh * L_ + gj) * HD_ + lc;
                h4 = *reinterpret_cast<const uint4*>(g_vh + o);
                l4 = *reinterpret_cast<const uint4*>(g_vl + o);
            }
            *reinterpret_cast<uint4*>(VH + row * FST_ + lc) = h4;
            *reinterpret_cast<uint4*>(VL + row * FST_ + lc) = l4;
        }
        if (nodetile && tid < 64) {
            int gj = j0 + tid;
            int nj = gj - TK_;
            int lo = (1 << 28), hi = -(1 << 28);
            if (nj < NK_ && gj < L_ && node_pad[b * NK_ + nj] == 0) {
                lo = node_indices[((size_t)bh * NK_ + nj) * 2 + 0];
                hi = node_indices[((size_t)bh * NK_ + nj) * 2 + 1];
            }
            clo[tid] = lo;
            chi[tid] = hi;
        }
        __syncthreads();

        float s[8][4];
        #pragma unroll
        for (int nf = 0; nf < 8; nf++) {
            s[nf][0] = 0.f; s[nf][1] = 0.f; s[nf][2] = 0.f; s[nf][3] = 0.f;
        }
        for (int kk = 0; kk < 8; kk++) {
            #pragma unroll
            for (int nf = 0; nf < 8; nf++) {
                int nb = (nf * 8 + g) * FST_ + kk * 8;
                uint32_t bhv[2] = {KH[nb + tig], KH[nb + tig + 4]};
                uint32_t blv[2] = {KL[nb + tig], KL[nb + tig + 4]};
                MMA_TF32(s[nf], qh[kk], bhv);
                MMA_TF32(s[nf], qh[kk], blv);
                MMA_TF32(s[nf], ql[kk], bhv);
            }
        }

        if (qleaf) {
            #pragma unroll
            for (int nf = 0; nf < 8; nf++) {
                int gj = j0 + nf * 8 + 2 * tig;
                if (key_pad[b * TK_ + gj])     { s[nf][0] = -1e30f; s[nf][2] = -1e30f; }
                if (key_pad[b * TK_ + gj + 1]) { s[nf][1] = -1e30f; s[nf][3] = -1e30f; }
            }
        } else if (!nodetile) {
            #pragma unroll
            for (int nf = 0; nf < 8; nf++) {
                int gj = j0 + nf * 8 + 2 * tig;
                bool kp0 = (key_pad[b * TK_ + gj] != 0);
                bool kp1 = (key_pad[b * TK_ + gj + 1] != 0);
                if (!(gj >= qloL0 && gj <= qhi0 && !kp0))             s[nf][0] = -1e30f;
                if (!((gj + 1) >= qloL0 && (gj + 1) <= qhi0 && !kp1)) s[nf][1] = -1e30f;
                if (!(gj >= qloL1 && gj <= qhi1 && !kp0))             s[nf][2] = -1e30f;
                if (!((gj + 1) >= qloL1 && (gj + 1) <= qhi1 && !kp1)) s[nf][3] = -1e30f;
            }
        } else {
            int nq0 = r0 - TK_, nq1 = r1 - TK_;
            #pragma unroll
            for (int nf = 0; nf < 8; nf++) {
                int cj = nf * 8 + 2 * tig;
                int nj0 = j0 + cj - TK_;
                int lo20 = clo[cj],     hi20 = chi[cj];
                int lo21 = clo[cj + 1], hi21 = chi[cj + 1];
                if (!(nj0 <= nq0 && max(qlo0, lo20) <= min(qhi0, hi20)))     s[nf][0] = -1e30f;
                if (!(nj0 + 1 <= nq0 && max(qlo0, lo21) <= min(qhi0, hi21))) s[nf][1] = -1e30f;
                if (!(nj0 <= nq1 && max(qlo1, lo20) <= min(qhi1, hi20)))     s[nf][2] = -1e30f;
                if (!(nj0 + 1 <= nq1 && max(qlo1, lo21) <= min(qhi1, hi21))) s[nf][3] = -1e30f;
            }
        }

        float tm0 = -1e30f, tm1 = -1e30f;
        #pragma unroll
        for (int nf = 0; nf < 8; nf++) {
            tm0 = fmaxf(tm0, fmaxf(s[nf][0], s[nf][1]));
            tm1 = fmaxf(tm1, fmaxf(s[nf][2], s[nf][3]));
        }
        tm0 = fmaxf(tm0, __shfl_xor_sync(0xffffffffu, tm0, 1));
        tm0 = fmaxf(tm0, __shfl_xor_sync(0xffffffffu, tm0, 2));
        tm1 = fmaxf(tm1, __shfl_xor_sync(0xffffffffu, tm1, 1));
        tm1 = fmaxf(tm1, __shfl_xor_sync(0xffffffffu, tm1, 2));

        float mn0 = fmaxf(m0, tm0);
        float mn1 = fmaxf(m1, tm1);
        float a0 = __expf(m0 - mn0);
        float a1 = __expf(m1 - mn1);
        m0 = mn0; m1 = mn1;
        float sb0 = fmaxf(mn0, -1e20f);
        float sb1 = fmaxf(mn1, -1e20f);

        float rs0 = 0.f, rs1 = 0.f;
        #pragma unroll
        for (int nf = 0; nf < 8; nf++) {
            s[nf][0] = __expf(s[nf][0] - sb0);
            s[nf][1] = __expf(s[nf][1] - sb0);
            s[nf][2] = __expf(s[nf][2] - sb1);
            s[nf][3] = __expf(s[nf][3] - sb1);
            rs0 += s[nf][0] + s[nf][1];
            rs1 += s[nf][2] + s[nf][3];
        }
        rs0 += __shfl_xor_sync(0xffffffffu, rs0, 1);
        rs0 += __shfl_xor_sync(0xffffffffu, rs0, 2);
        rs1 += __shfl_xor_sync(0xffffffffu, rs1, 1);
        rs1 += __shfl_xor_sync(0xffffffffu, rs1, 2);
        lsum0 = lsum0 * a0 + rs0;
        lsum1 = lsum1 * a1 + rs1;
        #pragma unroll
        for (int nf = 0; nf < 8; nf++) {
            acc[nf][0] *= a0; acc[nf][1] *= a0;
            acc[nf][2] *= a1; acc[nf][3] *= a1;
        }

        #pragma unroll
        for (int nf = 0; nf < 8; nf++) {
            int bg  = (wrow + g) * FST_ + nf * 8 + 2 * tig;
            int bg8 = (wrow + 8 + g) * FST_ + nf * 8 + 2 * tig;
            uint32_t h0, l0, h1, l1;
            split_tf32(s[nf][0], h0, l0);
            split_tf32(s[nf][1], h1, l1);
            *reinterpret_cast<uint2*>(PH + bg) = make_uint2(h0, h1);
            *reinterpret_cast<uint2*>(PL + bg) = make_uint2(l0, l1);
            split_tf32(s[nf][2], h0, l0);
            split_tf32(s[nf][3], h1, l1);
            *reinterpret_cast<uint2*>(PH + bg8) = make_uint2(h0, h1);
            *reinterpret_cast<uint2*>(PL + bg8) = make_uint2(l0, l1);
        }
        __syncwarp();

        for (int kk = 0; kk < 8; kk++) {
            int base0 = (wrow + g) * FST_ + kk * 8;
            int base1 = (wrow + 8 + g) * FST_ + kk * 8;
            uint32_t ah[4] = {PH[base0 + tig], PH[base1 + tig],
                              PH[base0 + tig + 4], PH[base1 + tig + 4]};
            uint32_t al[4] = {PL[base0 + tig], PL[base1 + tig],
                              PL[base0 + tig + 4], PL[base1 + tig + 4]};
            #pragma unroll
            for (int nf = 0; nf < 8; nf++) {
                int vb0 = (kk * 8 + tig) * FST_ + nf * 8 + g;
                int vb1 = (kk * 8 + tig + 4) * FST_ + nf * 8 + g;
                uint32_t bhv[2] = {VH[vb0], VH[vb1]};
                uint32_t blv[2] = {VL[vb0], VL[vb1]};
                MMA_TF32(acc[nf], ah, bhv);
                MMA_TF32(acc[nf], ah, blv);
                MMA_TF32(acc[nf], al, bhv);
            }
        }
    }

    float inv0 = 1.0f / lsum0;
    float inv1 = 1.0f / lsum1;
    #pragma unroll
    for (int nf = 0; nf < 8; nf++) {
        int d0 = nf * 8 + 2 * tig;
        if (r0 < L_) {
            float2 v = make_float2(acc[nf][0] * inv0, acc[nf][1] * inv0);
            *reinterpret_cast<float2*>(g_ao + ((size_t)(b * L_ + r0)) * D_ + h * HD_ + d0) = v;
        }
        if (r1 < L_) {
            float2 v = make_float2(acc[nf][2] * inv1, acc[nf][3] * inv1);
            *reinterpret_cast<float2*>(g_ao + ((size_t)(b * L_ + r1)) * D_ + h * HD_ + d0) = v;
        }
    }
}

// ---------------------------------------------------------------------------
extern "C" void kernel_launch(void* const* d_in, const int* in_sizes, int n_in,
                              void* d_out, int out_size)
{
    const float* leaves = (const float*)d_in[0];
    const float* nodes  = (const float*)d_in[1];
    const float* Wq     = (const float*)d_in[2];
    const float* Wk     = (const float*)d_in[3];
    const float* Wv     = (const float*)d_in[4];
    const float* Wo     = (const float*)d_in[5];
    const float* bq     = (const float*)d_in[6];
    const float* bk     = (const float*)d_in[7];
    const float* bv     = (const float*)d_in[8];
    const float* bo     = (const float*)d_in[9];
    const int*   node_indices = (const int*)d_in[10];
    const unsigned char* key_pad  = (const unsigned char*)d_in[11];
    const unsigned char* node_pad = (const unsigned char*)d_in[12];
    float* out = (float*)d_out;

    static int smem_set = 0;
    if (!smem_set) {
        cudaFuncSetAttribute(flash_mma_kernel,
                             cudaFuncAttributeMaxDynamicSharedMemorySize,
                             FLASH_SMEM);
        cudaFuncSetAttribute(qkv_mma_kernel,
                             cudaFuncAttributeMaxDynamicSharedMemorySize,
                             GEMM_SMEM_BYTES);
        cudaFuncSetAttribute(oproj_mma_kernel,
                             cudaFuncAttributeMaxDynamicSharedMemorySize,
                             GEMM_SMEM_BYTES);
        smem_set = 1;
    }

    qkv_mma_kernel<<<dim3(8, 32, 3), 256, GEMM_SMEM_BYTES>>>(
        leaves, nodes, Wq, Wk, Wv, bq, bk, bv);
    flash_mma_kernel<<<dim3(16, 32), 128, FLASH_SMEM>>>(node_indices, key_pad, node_pad);
    oproj_mma_kernel<<<dim3(8, 32), 256, GEMM_SMEM_BYTES>>>(Wo, bo, out);
}

// round 15
// speedup vs baseline: 1.1310x; 1.1310x over previous
#include <cuda_runtime.h>
#include <cstdint>

#define B_    4
#define H_    8
#define TK_   512
#define NK_   511
#define L_    1023
#define D_    512
#define HD_   64
#define BH_   32
#define ROWS_ 4092          // B_*L_

// Scratch (static __device__ — no allocations allowed)
__device__ float g_q[B_*H_*L_*HD_];
__device__ float g_k[B_*H_*L_*HD_];
__device__ float g_v[B_*H_*L_*HD_];
__device__ float g_ao[B_*L_*D_];            // attention output, (B,L, H*HD)

// ---------------------------------------------------------------------------
// tf32 helpers
// ---------------------------------------------------------------------------
__device__ __forceinline__ void split_tf32(float x, uint32_t& hi, uint32_t& lo)
{
    float h, l2;
    asm("cvt.rna.tf32.f32 %0, %1;" : "=f"(h) : "f"(x));
    float l = x - h;
    asm("cvt.rna.tf32.f32 %0, %1;" : "=f"(l2) : "f"(l));
    hi = __float_as_uint(h);
    lo = __float_as_uint(l2);
}

#define MMA_TF32(d, a, b)                                                     \
    asm volatile(                                                             \
        "mma.sync.aligned.m16n8k8.row.col.f32.tf32.tf32.f32 "                 \
        "{%0,%1,%2,%3}, {%4,%5,%6,%7}, {%8,%9}, {%0,%1,%2,%3};"               \
        : "+f"((d)[0]), "+f"((d)[1]), "+f"((d)[2]), "+f"((d)[3])              \
        : "r"((a)[0]), "r"((a)[1]), "r"((a)[2]), "r"((a)[3]),                 \
          "r"((b)[0]), "r"((b)[1]))

// ldmatrix x4: 4 8x8 b16 matrices; register layout == tf32 mma fragment.
#define LDSM_X4(R0, R1, R2, R3, ADDR)                                         \
    asm volatile("ldmatrix.sync.aligned.m8n8.x4.shared.b16 {%0,%1,%2,%3}, [%4];" \
        : "=r"(R0), "=r"(R1), "=r"(R2), "=r"(R3) : "r"(ADDR))

__device__ __forceinline__ uint32_t smem_u32(const void* p)
{
    return (uint32_t)__cvta_generic_to_shared(p);
}

// GEMM kernels: k-chunk = 32 -> stride 36
#define AST_ 36
#define GEMM_SMEM_BYTES ((2*128*AST_ + 2*64*AST_) * 4)   // 55296
// Flash tiles hold full k=64 -> stride 68
#define FST_ 68
#define FLASH_SMEM (6*64*FST_*4 + 2*64*4)                // 104960

// ---------------------------------------------------------------------------
// Kernel 1: fused QKV projection (round-11 verbatim — proven 330.7 build)
// ---------------------------------------------------------------------------
__global__ void __launch_bounds__(256, 2)
qkv_mma_kernel(const float* __restrict__ leaves,
               const float* __restrict__ nodes,
               const float* __restrict__ Wq,
               const float* __restrict__ Wk,
               const float* __restrict__ Wv,
               const float* __restrict__ bq,
               const float* __restrict__ bk,
               const float* __restrict__ bv)
{
    const int z = blockIdx.z;
    const float* W    = (z == 0) ? Wq : (z == 1) ? Wk : Wv;
    const float* bias = (z == 0) ? bq : (z == 1) ? bk : bv;
    float* out        = (z == 0) ? g_q : (z == 1) ? g_k : g_v;
    const float scale = (z == 0) ? 0.125f : 1.0f;

    extern __shared__ uint32_t smem_u[];
    uint32_t* AH = smem_u;
    uint32_t* AL = AH + 128 * AST_;
    uint32_t* BH = AL + 128 * AST_;
    uint32_t* BL = BH + 64 * AST_;

    const int tid  = threadIdx.x;
    const int warp = tid >> 5;
    const int lane = tid & 31;
    const int g    = lane >> 2;
    const int tig  = lane & 3;
    const int warpM = warp & 3;
    const int warpN = warp >> 2;
    const int M0 = warpM * 32;
    const int N0 = warpN * 32;

    const int r0 = blockIdx.y * 128;
    const int c0 = blockIdx.x * 64;

    const int lm = tid >> 3;
    const int lk = (tid & 7) * 4;

    const int r8 = lane & 7;
    const int mi = lane >> 3;
    const int rowA = (mi & 1) * 8 + r8, kA = (mi >> 1) * 4;
    const int rowB = (mi >> 1) * 8 + r8, kB = (mi & 1) * 4;
    const uint32_t ah_addr = smem_u32(AH) + (((M0 + rowA) * AST_ + kA) << 2);
    const uint32_t al_addr = smem_u32(AL) + (((M0 + rowA) * AST_ + kA) << 2);
    const uint32_t bh_addr = smem_u32(BH) + (((N0 + rowB) * AST_ + kB) << 2);
    const uint32_t bl_addr = smem_u32(BL) + (((N0 + rowB) * AST_ + kB) << 2);
    const uint32_t MT_STEP = (16 * AST_) << 2;

    const float* xsrc[4];
    #pragma unroll
    for (int p = 0; p < 4; p++) {
        int gr = r0 + lm + p * 32;
        if (gr < ROWS_) {
            int b = gr / L_, t = gr % L_;
            xsrc[p] = (t < TK_) ? (leaves + ((size_t)(b * TK_ + t)) * D_)
                                : (nodes  + ((size_t)(b * NK_ + (t - TK_))) * D_);
        } else xsrc[p] = nullptr;
    }
    const float* wsrc0 = W + (size_t)(c0 + lm) * D_;
    const float* wsrc1 = W + (size_t)(c0 + lm + 32) * D_;

    float acc[2][4][4] = {};

    float4 xa[4], wb[2];
    #pragma unroll
    for (int p = 0; p < 4; p++) {
        xa[p] = make_float4(0.f, 0.f, 0.f, 0.f);
        if (xsrc[p]) xa[p] = *reinterpret_cast<const float4*>(xsrc[p] + lk);
    }
    wb[0] = *reinterpret_cast<const float4*>(wsrc0 + lk);
    wb[1] = *reinterpret_cast<const float4*>(wsrc1 + lk);

    for (int k0 = 0; k0 < D_; k0 += 32) {
        __syncthreads();
        #pragma unroll
        for (int p = 0; p < 4; p++) {
            uint4 h4, l4;
            split_tf32(xa[p].x, h4.x, l4.x);
            split_tf32(xa[p].y, h4.y, l4.y);
            split_tf32(xa[p].z, h4.z, l4.z);
            split_tf32(xa[p].w, h4.w, l4.w);
            int m = lm + p * 32;
            *reinterpret_cast<uint4*>(AH + m * AST_ + lk) = h4;
            *reinterpret_cast<uint4*>(AL + m * AST_ + lk) = l4;
        }
        #pragma unroll
        for (int p = 0; p < 2; p++) {
            uint4 h4, l4;
            split_tf32(wb[p].x, h4.x, l4.x);
            split_tf32(wb[p].y, h4.y, l4.y);
            split_tf32(wb[p].z, h4.z, l4.z);
            split_tf32(wb[p].w, h4.w, l4.w);
            int n = lm + p * 32;
            *reinterpret_cast<uint4*>(BH + n * AST_ + lk) = h4;
            *reinterpret_cast<uint4*>(BL + n * AST_ + lk) = l4;
        }
        __syncthreads();

        if (k0 + 32 < D_) {
            #pragma unroll
            for (int p = 0; p < 4; p++) {
                if (xsrc[p]) xa[p] = *reinterpret_cast<const float4*>(xsrc[p] + k0 + 32 + lk);
            }
            wb[0] = *reinterpret_cast<const float4*>(wsrc0 + k0 + 32 + lk);
            wb[1] = *reinterpret_cast<const float4*>(wsrc1 + k0 + 32 + lk);
        }

        #pragma unroll
        for (int ks = 0; ks < 4; ks++) {
            const uint32_t koff = (ks * 8) << 2;
            uint32_t ah[2][4], al[2][4], bh[4][2], bl[4][2];
            LDSM_X4(ah[0][0], ah[0][1], ah[0][2], ah[0][3], ah_addr + koff);
            LDSM_X4(ah[1][0], ah[1][1], ah[1][2], ah[1][3], ah_addr + MT_STEP + koff);
            LDSM_X4(al[0][0], al[0][1], al[0][2], al[0][3], al_addr + koff);
            LDSM_X4(al[1][0], al[1][1], al[1][2], al[1][3], al_addr + MT_STEP + koff);
            uint32_t t0, t1, t2, t3;
            LDSM_X4(t0, t1, t2, t3, bh_addr + koff);
            bh[0][0] = t0; bh[0][1] = t1; bh[1][0] = t2; bh[1][1] = t3;
            LDSM_X4(t0, t1, t2, t3, bh_addr + MT_STEP + koff);
            bh[2][0] = t0; bh[2][1] = t1; bh[3][0] = t2; bh[3][1] = t3;
            LDSM_X4(t0, t1, t2, t3, bl_addr + koff);
            bl[0][0] = t0; bl[0][1] = t1; bl[1][0] = t2; bl[1][1] = t3;
            LDSM_X4(t0, t1, t2, t3, bl_addr + MT_STEP + koff);
            bl[2][0] = t0; bl[2][1] = t1; bl[3][0] = t2; bl[3][1] = t3;

            #pragma unroll
            for (int mt = 0; mt < 2; mt++)
                #pragma unroll
                for (int nt = 0; nt < 4; nt++) {
                    MMA_TF32(acc[mt][nt], ah[mt], bh[nt]);
                    MMA_TF32(acc[mt][nt], ah[mt], bl[nt]);
                    MMA_TF32(acc[mt][nt], al[mt], bh[nt]);
                }
        }
    }

    #pragma unroll
    for (int mt = 0; mt < 2; mt++)
        #pragma unroll
        for (int nt = 0; nt < 4; nt++) {
            int col = N0 + nt * 8 + tig * 2;
            int gc = c0 + col;
            int h = gc >> 6, d = gc & 63;
            float b0v = bias[gc], b1v = bias[gc + 1];
            #pragma unroll
            for (int hh = 0; hh < 2; hh++) {
                int gr = r0 + M0 + mt * 16 + g + hh * 8;
                if (gr >= ROWS_) continue;
                int b = gr / L_, l = gr % L_;
                float v0 = (acc[mt][nt][hh * 2 + 0] + b0v) * scale;
                float v1 = (acc[mt][nt][hh * 2 + 1] + b1v) * scale;
                float* dst = out + (((size_t)(b * H_ + h)) * L_ + l) * HD_ + d;
                dst[0] = v0;
                dst[1] = v1;
            }
        }
}

// ---------------------------------------------------------------------------
// Kernel 3: out = g_ao @ Wo^T + bo  (round-11 verbatim)
// ---------------------------------------------------------------------------
__global__ void __launch_bounds__(256, 2)
oproj_mma_kernel(const float* __restrict__ Wo,
                 const float* __restrict__ bo,
                 float* __restrict__ out)
{
    extern __shared__ uint32_t smem_u[];
    uint32_t* AH = smem_u;
    uint32_t* AL = AH + 128 * AST_;
    uint32_t* BH = AL + 128 * AST_;
    uint32_t* BL = BH + 64 * AST_;

    const int tid  = threadIdx.x;
    const int warp = tid >> 5;
    const int lane = tid & 31;
    const int g    = lane >> 2;
    const int tig  = lane & 3;
    const int warpM = warp & 3;
    const int warpN = warp >> 2;
    const int M0 = warpM * 32;
    const int N0 = warpN * 32;

    const int r0 = blockIdx.y * 128;
    const int c0 = blockIdx.x * 64;

    const int lm = tid >> 3;
    const int lk = (tid & 7) * 4;

    const int r8 = lane & 7;
    const int mi = lane >> 3;
    const int rowA = (mi & 1) * 8 + r8, kA = (mi >> 1) * 4;
    const int rowB = (mi >> 1) * 8 + r8, kB = (mi & 1) * 4;
    const uint32_t ah_addr = smem_u32(AH) + (((M0 + rowA) * AST_ + kA) << 2);
    const uint32_t al_addr = smem_u32(AL) + (((M0 + rowA) * AST_ + kA) << 2);
    const uint32_t bh_addr = smem_u32(BH) + (((N0 + rowB) * AST_ + kB) << 2);
    const uint32_t bl_addr = smem_u32(BL) + (((N0 + rowB) * AST_ + kB) << 2);
    const uint32_t MT_STEP = (16 * AST_) << 2;

    const float* xsrc[4];
    #pragma unroll
    for (int p = 0; p < 4; p++) {
        int gr = r0 + lm + p * 32;
        xsrc[p] = (gr < ROWS_) ? (g_ao + (size_t)gr * D_) : nullptr;
    }
    const float* wsrc0 = Wo + (size_t)(c0 + lm) * D_;
    const float* wsrc1 = Wo + (size_t)(c0 + lm + 32) * D_;

    float acc[2][4][4] = {};

    float4 xa[4], wb[2];
    #pragma unroll
    for (int p = 0; p < 4; p++) {
        xa[p] = make_float4(0.f, 0.f, 0.f, 0.f);
        if (xsrc[p]) xa[p] = *reinterpret_cast<const float4*>(xsrc[p] + lk);
    }
    wb[0] = *reinterpret_cast<const float4*>(wsrc0 + lk);
    wb[1] = *reinterpret_cast<const float4*>(wsrc1 + lk);

    for (int k0 = 0; k0 < D_; k0 += 32) {
        __syncthreads();
        #pragma unroll
        for (int p = 0; p < 4; p++) {
            uint4 h4, l4;
            split_tf32(xa[p].x, h4.x, l4.x);
            split_tf32(xa[p].y, h4.y, l4.y);
            split_tf32(xa[p].z, h4.z, l4.z);
            split_tf32(xa[p].w, h4.w, l4.w);
            int m = lm + p * 32;
            *reinterpret_cast<uint4*>(AH + m * AST_ + lk) = h4;
            *reinterpret_cast<uint4*>(AL + m * AST_ + lk) = l4;
        }
        #pragma unroll
        for (int p = 0; p < 2; p++) {
            uint4 h4, l4;
            split_tf32(wb[p].x, h4.x, l4.x);
            split_tf32(wb[p].y, h4.y, l4.y);
            split_tf32(wb[p].z, h4.z, l4.z);
            split_tf32(wb[p].w, h4.w, l4.w);
            int n = lm + p * 32;
            *reinterpret_cast<uint4*>(BH + n * AST_ + lk) = h4;
            *reinterpret_cast<uint4*>(BL + n * AST_ + lk) = l4;
        }
        __syncthreads();

        if (k0 + 32 < D_) {
            #pragma unroll
            for (int p = 0; p < 4; p++) {
                if (xsrc[p]) xa[p] = *reinterpret_cast<const float4*>(xsrc[p] + k0 + 32 + lk);
            }
            wb[0] = *reinterpret_cast<const float4*>(wsrc0 + k0 + 32 + lk);
            wb[1] = *reinterpret_cast<const float4*>(wsrc1 + k0 + 32 + lk);
        }

        #pragma unroll
        for (int ks = 0; ks < 4; ks++) {
            const uint32_t koff = (ks * 8) << 2;
            uint32_t ah[2][4], al[2][4], bh[4][2], bl[4][2];
            LDSM_X4(ah[0][0], ah[0][1], ah[0][2], ah[0][3], ah_addr + koff);
            LDSM_X4(ah[1][0], ah[1][1], ah[1][2], ah[1][3], ah_addr + MT_STEP + koff);
            LDSM_X4(al[0][0], al[0][1], al[0][2], al[0][3], al_addr + koff);
            LDSM_X4(al[1][0], al[1][1], al[1][2], al[1][3], al_addr + MT_STEP + koff);
            uint32_t t0, t1, t2, t3;
            LDSM_X4(t0, t1, t2, t3, bh_addr + koff);
            bh[0][0] = t0; bh[0][1] = t1; bh[1][0] = t2; bh[1][1] = t3;
            LDSM_X4(t0, t1, t2, t3, bh_addr + MT_STEP + koff);
            bh[2][0] = t0; bh[2][1] = t1; bh[3][0] = t2; bh[3][1] = t3;
            LDSM_X4(t0, t1, t2, t3, bl_addr + koff);
            bl[0][0] = t0; bl[0][1] = t1; bl[1][0] = t2; bl[1][1] = t3;
            LDSM_X4(t0, t1, t2, t3, bl_addr + MT_STEP + koff);
            bl[2][0] = t0; bl[2][1] = t1; bl[3][0] = t2; bl[3][1] = t3;

            #pragma unroll
            for (int mt = 0; mt < 2; mt++)
                #pragma unroll
                for (int nt = 0; nt < 4; nt++) {
                    MMA_TF32(acc[mt][nt], ah[mt], bh[nt]);
                    MMA_TF32(acc[mt][nt], ah[mt], bl[nt]);
                    MMA_TF32(acc[mt][nt], al[mt], bh[nt]);
                }
        }
    }

    #pragma unroll
    for (int mt = 0; mt < 2; mt++)
        #pragma unroll
        for (int nt = 0; nt < 4; nt++) {
            int gc = c0 + N0 + nt * 8 + tig * 2;
            float b0v = bo[gc], b1v = bo[gc + 1];
            #pragma unroll
            for (int hh = 0; hh < 2; hh++) {
                int gr = r0 + M0 + mt * 16 + g + hh * 8;
                if (gr >= ROWS_) continue;
                float* dst = out + (size_t)gr * D_ + gc;
                dst[0] = acc[mt][nt][hh * 2 + 0] + b0v;
                dst[1] = acc[mt][nt][hh * 2 + 1] + b1v;
            }
        }
}

// ---------------------------------------------------------------------------
// Kernel 2: flash attention — round-7 body VERBATIM; only the grid mapping
// changes: grid = (32 bh, 16 tiles), i0 = (15 - by)*64 so the heaviest
// (node-query) blocks launch first (LPT schedule).
// ---------------------------------------------------------------------------
__global__ void flash_mma_kernel(const int* __restrict__ node_indices,
                                 const unsigned char* __restrict__ key_pad,
                                 const unsigned char* __restrict__ node_pad)
{
    extern __shared__ uint32_t sm[];
    uint32_t* KH = sm;
    uint32_t* KL = KH + 64 * FST_;
    uint32_t* VH = KL + 64 * FST_;
    uint32_t* VL = VH + 64 * FST_;
    uint32_t* PH = VL + 64 * FST_;
    uint32_t* PL = PH + 64 * FST_;
    int* clo = (int*)(PL + 64 * FST_);
    int* chi = clo + 64;

    const int bh = blockIdx.x;                    // 0..31
    const int b  = bh >> 3;
    const int h  = bh & 7;
    const int i0 = (15 - (int)blockIdx.y) * 64;   // heavy blocks first
    const bool qleaf = (i0 < TK_);

    const int tid  = threadIdx.x;       // 128
    const int warp = tid >> 5;
    const int lane = tid & 31;
    const int g    = lane >> 2;
    const int tig  = lane & 3;
    const int wrow = warp * 16;

    const int lj = tid >> 4;            // 0..7
    const int lc = (tid & 15) * 4;      // 0,4,...,60

    #pragma unroll
    for (int p = 0; p < 8; p++) {
        int row = p * 8 + lj;
        int gi = i0 + row;
        float4 qv = make_float4(0.f, 0.f, 0.f, 0.f);
        if (gi < L_)
            qv = *reinterpret_cast<const float4*>(g_q + ((size_t)bh * L_ + gi) * HD_ + lc);
        uint4 h4, l4;
        split_tf32(qv.x, h4.x, l4.x);
        split_tf32(qv.y, h4.y, l4.y);
        split_tf32(qv.z, h4.z, l4.z);
        split_tf32(qv.w, h4.w, l4.w);
        *reinterpret_cast<uint4*>(PH + row * FST_ + lc) = h4;
        *reinterpret_cast<uint4*>(PL + row * FST_ + lc) = l4;
    }
    __syncthreads();

    uint32_t qh[8][4], ql[8][4];
    #pragma unroll
    for (int kk = 0; kk < 8; kk++) {
        int base0 = (wrow + g) * FST_ + kk * 8;
        int base1 = (wrow + 8 + g) * FST_ + kk * 8;
        qh[kk][0] = PH[base0 + tig];
        qh[kk][1] = PH[base1 + tig];
        qh[kk][2] = PH[base0 + tig + 4];
        qh[kk][3] = PH[base1 + tig + 4];
        ql[kk][0] = PL[base0 + tig];
        ql[kk][1] = PL[base1 + tig];
        ql[kk][2] = PL[base0 + tig + 4];
        ql[kk][3] = PL[base1 + tig + 4];
    }

    const int r0 = i0 + wrow + g;
    const int r1 = r0 + 8;
    int qlo0 = 0, qhi0 = 0, qloL0 = 0, qlo1 = 0, qhi1 = 0, qloL1 = 0;
    if (!qleaf) {
        int nq0 = min(r0 - TK_, NK_ - 1);
        qlo0 = node_indices[((size_t)bh * NK_ + nq0) * 2 + 0];
        qhi0 = node_indices[((size_t)bh * NK_ + nq0) * 2 + 1];
        qloL0 = (node_pad[b * NK_ + nq0] != 0) ? (1 << 28) : qlo0;
        int nq1 = min(r1 - TK_, NK_ - 1);
        qlo1 = node_indices[((size_t)bh * NK_ + nq1) * 2 + 0];
        qhi1 = node_indices[((size_t)bh * NK_ + nq1) * 2 + 1];
        qloL1 = (node_pad[b * NK_ + nq1] != 0) ? (1 << 28) : qlo1;
    }

    float m0 = -1e30f, m1 = -1e30f, lsum0 = 0.f, lsum1 = 0.f;
    float acc[8][4] = {};

    const int ntiles = qleaf ? 8 : (9 + (i0 - TK_) / 64);
    for (int jt = 0; jt < ntiles; jt++) {
        const bool nodetile = (jt >= 8);
        const int j0 = nodetile ? TK_ + (jt - 8) * 64 : jt * 64;

        __syncthreads();
        #pragma unroll
        for (int p = 0; p < 8; p++) {
            int row = p * 8 + lj;
            int gj = j0 + row;
            float4 kv = make_float4(0.f, 0.f, 0.f, 0.f);
            if (gj < L_)
                kv = *reinterpret_cast<const float4*>(g_k + ((size_t)bh * L_ + gj) * HD_ + lc);
            uint4 h4, l4;
            split_tf32(kv.x, h4.x, l4.x);
            split_tf32(kv.y, h4.y, l4.y);
            split_tf32(kv.z, h4.z, l4.z);
            split_tf32(kv.w, h4.w, l4.w);
            *reinterpret_cast<uint4*>(KH + row * FST_ + lc) = h4;
            *reinterpret_cast<uint4*>(KL + row * FST_ + lc) = l4;
        }
        #pragma unroll
        for (int p = 0; p < 8; p++) {
            int row = p * 8 + lj;
            int gj = j0 + row;
            float4 vv = make_float4(0.f, 0.f, 0.f, 0.f);
            if (gj < L_)
                vv = *reinterpret_cast<const float4*>(g_v + ((size_t)bh * L_ + gj) * HD_ + lc);
            uint4 h4, l4;
            split_tf32(vv.x, h4.x, l4.x);
            split_tf32(vv.y, h4.y, l4.y);
            split_tf32(vv.z, h4.z, l4.z);
            split_tf32(vv.w, h4.w, l4.w);
            *reinterpret_cast<uint4*>(VH + row * FST_ + lc) = h4;
            *reinterpret_cast<uint4*>(VL + row * FST_ + lc) = l4;
        }
        if (nodetile && tid < 64) {
            int gj = j0 + tid;
            int nj = gj - TK_;
            int lo = (1 << 28), hi = -(1 << 28);
            if (nj < NK_ && gj < L_ && node_pad[b * NK_ + nj] == 0) {
                lo = node_indices[((size_t)bh * NK_ + nj) * 2 + 0];
                hi = node_indices[((size_t)bh * NK_ + nj) * 2 + 1];
            }
            clo[tid] = lo;
            chi[tid] = hi;
        }
        __syncthreads();

        float s[8][4];
        #pragma unroll
        for (int nf = 0; nf < 8; nf++) {
            s[nf][0] = 0.f; s[nf][1] = 0.f; s[nf][2] = 0.f; s[nf][3] = 0.f;
        }
        for (int kk = 0; kk < 8; kk++) {
            #pragma unroll
            for (int nf = 0; nf < 8; nf++) {
                int nb = (nf * 8 + g) * FST_ + kk * 8;
                uint32_t bhv[2] = {KH[nb + tig], KH[nb + tig + 4]};
                uint32_t blv[2] = {KL[nb + tig], KL[nb + tig + 4]};
                MMA_TF32(s[nf], qh[kk], bhv);
                MMA_TF32(s[nf], qh[kk], blv);
                MMA_TF32(s[nf], ql[kk], bhv);
            }
        }

        if (qleaf) {
            #pragma unroll
            for (int nf = 0; nf < 8; nf++) {
                int gj = j0 + nf * 8 + 2 * tig;
                if (key_pad[b * TK_ + gj])     { s[nf][0] = -1e30f; s[nf][2] = -1e30f; }
                if (key_pad[b * TK_ + gj + 1]) { s[nf][1] = -1e30f; s[nf][3] = -1e30f; }
            }
        } else if (!nodetile) {
            #pragma unroll
            for (int nf = 0; nf < 8; nf++) {
                int gj = j0 + nf * 8 + 2 * tig;
                bool kp0 = (key_pad[b * TK_ + gj] != 0);
                bool kp1 = (key_pad[b * TK_ + gj + 1] != 0);
                if (!(gj >= qloL0 && gj <= qhi0 && !kp0))             s[nf][0] = -1e30f;
                if (!((gj + 1) >= qloL0 && (gj + 1) <= qhi0 && !kp1)) s[nf][1] = -1e30f;
                if (!(gj >= qloL1 && gj <= qhi1 && !kp0))             s[nf][2] = -1e30f;
                if (!((gj + 1) >= qloL1 && (gj + 1) <= qhi1 && !kp1)) s[nf][3] = -1e30f;
            }
        } else {
            int nq0 = r0 - TK_, nq1 = r1 - TK_;
            #pragma unroll
            for (int nf = 0; nf < 8; nf++) {
                int cj = nf * 8 + 2 * tig;
                int nj0 = j0 + cj - TK_;
                int lo20 = clo[cj],     hi20 = chi[cj];
                int lo21 = clo[cj + 1], hi21 = chi[cj + 1];
                if (!(nj0 <= nq0 && max(qlo0, lo20) <= min(qhi0, hi20)))     s[nf][0] = -1e30f;
                if (!(nj0 + 1 <= nq0 && max(qlo0, lo21) <= min(qhi0, hi21))) s[nf][1] = -1e30f;
                if (!(nj0 <= nq1 && max(qlo1, lo20) <= min(qhi1, hi20)))     s[nf][2] = -1e30f;
                if (!(nj0 + 1 <= nq1 && max(qlo1, lo21) <= min(qhi1, hi21))) s[nf][3] = -1e30f;
            }
        }

        float tm0 = -1e30f, tm1 = -1e30f;
        #pragma unroll
        for (int nf = 0; nf < 8; nf++) {
            tm0 = fmaxf(tm0, fmaxf(s[nf][0], s[nf][1]));
            tm1 = fmaxf(tm1, fmaxf(s[nf][2], s[nf][3]));
        }
        tm0 = fmaxf(tm0, __shfl_xor_sync(0xffffffffu, tm0, 1));
        tm0 = fmaxf(tm0, __shfl_xor_sync(0xffffffffu, tm0, 2));
        tm1 = fmaxf(tm1, __shfl_xor_sync(0xffffffffu, tm1, 1));
        tm1 = fmaxf(tm1, __shfl_xor_sync(0xffffffffu, tm1, 2));

        float mn0 = fmaxf(m0, tm0);
        float mn1 = fmaxf(m1, tm1);
        float a0 = __expf(m0 - mn0);
        float a1 = __expf(m1 - mn1);
        m0 = mn0; m1 = mn1;
        float sb0 = fmaxf(mn0, -1e20f);
        float sb1 = fmaxf(mn1, -1e20f);

        float rs0 = 0.f, rs1 = 0.f;
        #pragma unroll
        for (int nf = 0; nf < 8; nf++) {
            s[nf][0] = __expf(s[nf][0] - sb0);
            s[nf][1] = __expf(s[nf][1] - sb0);
            s[nf][2] = __expf(s[nf][2] - sb1);
            s[nf][3] = __expf(s[nf][3] - sb1);
            rs0 += s[nf][0] + s[nf][1];
            rs1 += s[nf][2] + s[nf][3];
        }
        rs0 += __shfl_xor_sync(0xffffffffu, rs0, 1);
        rs0 += __shfl_xor_sync(0xffffffffu, rs0, 2);
        rs1 += __shfl_xor_sync(0xffffffffu, rs1, 1);
        rs1 += __shfl_xor_sync(0xffffffffu, rs1, 2);
        lsum0 = lsum0 * a0 + rs0;
        lsum1 = lsum1 * a1 + rs1;
        #pragma unroll
        for (int nf = 0; nf < 8; nf++) {
            acc[nf][0] *= a0; acc[nf][1] *= a0;
            acc[nf][2] *= a1; acc[nf][3] *= a1;
        }

        #pragma unroll
        for (int nf = 0; nf < 8; nf++) {
            int bg  = (wrow + g) * FST_ + nf * 8 + 2 * tig;
            int bg8 = (wrow + 8 + g) * FST_ + nf * 8 + 2 * tig;
            uint32_t h0, l0, h1, l1;
            split_tf32(s[nf][0], h0, l0);
            split_tf32(s[nf][1], h1, l1);
            *reinterpret_cast<uint2*>(PH + bg) = make_uint2(h0, h1);
            *reinterpret_cast<uint2*>(PL + bg) = make_uint2(l0, l1);
            split_tf32(s[nf][2], h0, l0);
            split_tf32(s[nf][3], h1, l1);
            *reinterpret_cast<uint2*>(PH + bg8) = make_uint2(h0, h1);
            *reinterpret_cast<uint2*>(PL + bg8) = make_uint2(l0, l1);
        }
        __syncwarp();

        for (int kk = 0; kk < 8; kk++) {
            int base0 = (wrow + g) * FST_ + kk * 8;
            int base1 = (wrow + 8 + g) * FST_ + kk * 8;
            uint32_t ah[4] = {PH[base0 + tig], PH[base1 + tig],
                              PH[base0 + tig + 4], PH[base1 + tig + 4]};
            uint32_t al[4] = {PL[base0 + tig], PL[base1 + tig],
                              PL[base0 + tig + 4], PL[base1 + tig + 4]};
            #pragma unroll
            for (int nf = 0; nf < 8; nf++) {
                int vb0 = (kk * 8 + tig) * FST_ + nf * 8 + g;
                int vb1 = (kk * 8 + tig + 4) * FST_ + nf * 8 + g;
                uint32_t bhv[2] = {VH[vb0], VH[vb1]};
                uint32_t blv[2] = {VL[vb0], VL[vb1]};
                MMA_TF32(acc[nf], ah, bhv);
                MMA_TF32(acc[nf], ah, blv);
                MMA_TF32(acc[nf], al, bhv);
            }
        }
    }

    float inv0 = 1.0f / lsum0;
    float inv1 = 1.0f / lsum1;
    #pragma unroll
    for (int nf = 0; nf < 8; nf++) {
        int d0 = nf * 8 + 2 * tig;
        if (r0 < L_) {
            float2 v = make_float2(acc[nf][0] * inv0, acc[nf][1] * inv0);
            *reinterpret_cast<float2*>(g_ao + ((size_t)(b * L_ + r0)) * D_ + h * HD_ + d0) = v;
        }
        if (r1 < L_) {
            float2 v = make_float2(acc[nf][2] * inv1, acc[nf][3] * inv1);
            *reinterpret_cast<float2*>(g_ao + ((size_t)(b * L_ + r1)) * D_ + h * HD_ + d0) = v;
        }
    }
}

// ---------------------------------------------------------------------------
extern "C" void kernel_launch(void* const* d_in, const int* in_sizes, int n_in,
                              void* d_out, int out_size)
{
    const float* leaves = (const float*)d_in[0];
    const float* nodes  = (const float*)d_in[1];
    const float* Wq     = (const float*)d_in[2];
    const float* Wk     = (const float*)d_in[3];
    const float* Wv     = (const float*)d_in[4];
    const float* Wo     = (const float*)d_in[5];
    const float* bq     = (const float*)d_in[6];
    const float* bk     = (const float*)d_in[7];
    const float* bv     = (const float*)d_in[8];
    const float* bo     = (const float*)d_in[9];
    const int*   node_indices = (const int*)d_in[10];
    const unsigned char* key_pad  = (const unsigned char*)d_in[11];
    const unsigned char* node_pad = (const unsigned char*)d_in[12];
    float* out = (float*)d_out;

    static int smem_set = 0;
    if (!smem_set) {
        cudaFuncSetAttribute(flash_mma_kernel,
                             cudaFuncAttributeMaxDynamicSharedMemorySize,
                             FLASH_SMEM);
        cudaFuncSetAttribute(qkv_mma_kernel,
                             cudaFuncAttributeMaxDynamicSharedMemorySize,
                             GEMM_SMEM_BYTES);
        cudaFuncSetAttribute(oproj_mma_kernel,
                             cudaFuncAttributeMaxDynamicSharedMemorySize,
                             GEMM_SMEM_BYTES);
        smem_set = 1;
    }

    qkv_mma_kernel<<<dim3(8, 32, 3), 256, GEMM_SMEM_BYTES>>>(
        leaves, nodes, Wq, Wk, Wv, bq, bk, bv);
    flash_mma_kernel<<<dim3(32, 16), 128, FLASH_SMEM>>>(node_indices, key_pad, node_pad);
    oproj_mma_kernel<<<dim3(8, 32), 256, GEMM_SMEM_BYTES>>>(Wo, bo, out);
}

// round 16
// speedup vs baseline: 1.2418x; 1.0980x over previous
#include <cuda_runtime.h>
#include <cstdint>

#define B_    4
#define H_    8
#define TK_   512
#define NK_   511
#define L_    1023
#define D_    512
#define HD_   64
#define BH_   32
#define ROWS_ 4092          // B_*L_

// Scratch (static __device__ — no allocations allowed)
__device__ float g_q[B_*H_*L_*HD_];
__device__ float g_k[B_*H_*L_*HD_];
__device__ float g_v[B_*H_*L_*HD_];
__device__ float g_ao[B_*L_*D_];            // attention output, (B,L, H*HD)

// ---------------------------------------------------------------------------
// tf32 helpers
// ---------------------------------------------------------------------------
__device__ __forceinline__ void split_tf32(float x, uint32_t& hi, uint32_t& lo)
{
    float h, l2;
    asm("cvt.rna.tf32.f32 %0, %1;" : "=f"(h) : "f"(x));
    float l = x - h;
    asm("cvt.rna.tf32.f32 %0, %1;" : "=f"(l2) : "f"(l));
    hi = __float_as_uint(h);
    lo = __float_as_uint(l2);
}

__device__ __forceinline__ uint32_t cvt_tf32(float x)
{
    float h;
    asm("cvt.rna.tf32.f32 %0, %1;" : "=f"(h) : "f"(x));
    return __float_as_uint(h);
}

#define MMA_TF32(d, a, b)                                                     \
    asm volatile(                                                             \
        "mma.sync.aligned.m16n8k8.row.col.f32.tf32.tf32.f32 "                 \
        "{%0,%1,%2,%3}, {%4,%5,%6,%7}, {%8,%9}, {%0,%1,%2,%3};"               \
        : "+f"((d)[0]), "+f"((d)[1]), "+f"((d)[2]), "+f"((d)[3])              \
        : "r"((a)[0]), "r"((a)[1]), "r"((a)[2]), "r"((a)[3]),                 \
          "r"((b)[0]), "r"((b)[1]))

// ldmatrix x4: 4 8x8 b16 matrices; register layout == tf32 mma fragment.
#define LDSM_X4(R0, R1, R2, R3, ADDR)                                         \
    asm volatile("ldmatrix.sync.aligned.m8n8.x4.shared.b16 {%0,%1,%2,%3}, [%4];" \
        : "=r"(R0), "=r"(R1), "=r"(R2), "=r"(R3) : "r"(ADDR))

__device__ __forceinline__ uint32_t smem_u32(const void* p)
{
    return (uint32_t)__cvta_generic_to_shared(p);
}

// GEMM kernels: k-chunk = 32 -> stride 36
#define AST_ 36
#define GEMM_SMEM_BYTES ((2*128*AST_ + 2*64*AST_) * 4)   // 55296
// Flash tiles hold full k=64 -> stride 68
#define FST_ 68
#define FLASH_SMEM (6*64*FST_*4 + 2*64*4)                // 104960

// ---------------------------------------------------------------------------
// Kernel 1: fused QKV projection (round-11 verbatim — proven)
// ---------------------------------------------------------------------------
__global__ void __launch_bounds__(256, 2)
qkv_mma_kernel(const float* __restrict__ leaves,
               const float* __restrict__ nodes,
               const float* __restrict__ Wq,
               const float* __restrict__ Wk,
               const float* __restrict__ Wv,
               const float* __restrict__ bq,
               const float* __restrict__ bk,
               const float* __restrict__ bv)
{
    const int z = blockIdx.z;
    const float* W    = (z == 0) ? Wq : (z == 1) ? Wk : Wv;
    const float* bias = (z == 0) ? bq : (z == 1) ? bk : bv;
    float* out        = (z == 0) ? g_q : (z == 1) ? g_k : g_v;
    const float scale = (z == 0) ? 0.125f : 1.0f;

    extern __shared__ uint32_t smem_u[];
    uint32_t* AH = smem_u;
    uint32_t* AL = AH + 128 * AST_;
    uint32_t* BH = AL + 128 * AST_;
    uint32_t* BL = BH + 64 * AST_;

    const int tid  = threadIdx.x;
    const int warp = tid >> 5;
    const int lane = tid & 31;
    const int g    = lane >> 2;
    const int tig  = lane & 3;
    const int warpM = warp & 3;
    const int warpN = warp >> 2;
    const int M0 = warpM * 32;
    const int N0 = warpN * 32;

    const int r0 = blockIdx.y * 128;
    const int c0 = blockIdx.x * 64;

    const int lm = tid >> 3;
    const int lk = (tid & 7) * 4;

    const int r8 = lane & 7;
    const int mi = lane >> 3;
    const int rowA = (mi & 1) * 8 + r8, kA = (mi >> 1) * 4;
    const int rowB = (mi >> 1) * 8 + r8, kB = (mi & 1) * 4;
    const uint32_t ah_addr = smem_u32(AH) + (((M0 + rowA) * AST_ + kA) << 2);
    const uint32_t al_addr = smem_u32(AL) + (((M0 + rowA) * AST_ + kA) << 2);
    const uint32_t bh_addr = smem_u32(BH) + (((N0 + rowB) * AST_ + kB) << 2);
    const uint32_t bl_addr = smem_u32(BL) + (((N0 + rowB) * AST_ + kB) << 2);
    const uint32_t MT_STEP = (16 * AST_) << 2;

    const float* xsrc[4];
    #pragma unroll
    for (int p = 0; p < 4; p++) {
        int gr = r0 + lm + p * 32;
        if (gr < ROWS_) {
            int b = gr / L_, t = gr % L_;
            xsrc[p] = (t < TK_) ? (leaves + ((size_t)(b * TK_ + t)) * D_)
                                : (nodes  + ((size_t)(b * NK_ + (t - TK_))) * D_);
        } else xsrc[p] = nullptr;
    }
    const float* wsrc0 = W + (size_t)(c0 + lm) * D_;
    const float* wsrc1 = W + (size_t)(c0 + lm + 32) * D_;

    float acc[2][4][4] = {};

    float4 xa[4], wb[2];
    #pragma unroll
    for (int p = 0; p < 4; p++) {
        xa[p] = make_float4(0.f, 0.f, 0.f, 0.f);
        if (xsrc[p]) xa[p] = *reinterpret_cast<const float4*>(xsrc[p] + lk);
    }
    wb[0] = *reinterpret_cast<const float4*>(wsrc0 + lk);
    wb[1] = *reinterpret_cast<const float4*>(wsrc1 + lk);

    for (int k0 = 0; k0 < D_; k0 += 32) {
        __syncthreads();
        #pragma unroll
        for (int p = 0; p < 4; p++) {
            uint4 h4, l4;
            split_tf32(xa[p].x, h4.x, l4.x);
            split_tf32(xa[p].y, h4.y, l4.y);
            split_tf32(xa[p].z, h4.z, l4.z);
            split_tf32(xa[p].w, h4.w, l4.w);
            int m = lm + p * 32;
            *reinterpret_cast<uint4*>(AH + m * AST_ + lk) = h4;
            *reinterpret_cast<uint4*>(AL + m * AST_ + lk) = l4;
        }
        #pragma unroll
        for (int p = 0; p < 2; p++) {
            uint4 h4, l4;
            split_tf32(wb[p].x, h4.x, l4.x);
            split_tf32(wb[p].y, h4.y, l4.y);
            split_tf32(wb[p].z, h4.z, l4.z);
            split_tf32(wb[p].w, h4.w, l4.w);
            int n = lm + p * 32;
            *reinterpret_cast<uint4*>(BH + n * AST_ + lk) = h4;
            *reinterpret_cast<uint4*>(BL + n * AST_ + lk) = l4;
        }
        __syncthreads();

        if (k0 + 32 < D_) {
            #pragma unroll
            for (int p = 0; p < 4; p++) {
                if (xsrc[p]) xa[p] = *reinterpret_cast<const float4*>(xsrc[p] + k0 + 32 + lk);
            }
            wb[0] = *reinterpret_cast<const float4*>(wsrc0 + k0 + 32 + lk);
            wb[1] = *reinterpret_cast<const float4*>(wsrc1 + k0 + 32 + lk);
        }

        #pragma unroll
        for (int ks = 0; ks < 4; ks++) {
            const uint32_t koff = (ks * 8) << 2;
            uint32_t ah[2][4], al[2][4], bh[4][2], bl[4][2];
            LDSM_X4(ah[0][0], ah[0][1], ah[0][2], ah[0][3], ah_addr + koff);
            LDSM_X4(ah[1][0], ah[1][1], ah[1][2], ah[1][3], ah_addr + MT_STEP + koff);
            LDSM_X4(al[0][0], al[0][1], al[0][2], al[0][3], al_addr + koff);
            LDSM_X4(al[1][0], al[1][1], al[1][2], al[1][3], al_addr + MT_STEP + koff);
            uint32_t t0, t1, t2, t3;
            LDSM_X4(t0, t1, t2, t3, bh_addr + koff);
            bh[0][0] = t0; bh[0][1] = t1; bh[1][0] = t2; bh[1][1] = t3;
            LDSM_X4(t0, t1, t2, t3, bh_addr + MT_STEP + koff);
            bh[2][0] = t0; bh[2][1] = t1; bh[3][0] = t2; bh[3][1] = t3;
            LDSM_X4(t0, t1, t2, t3, bl_addr + koff);
            bl[0][0] = t0; bl[0][1] = t1; bl[1][0] = t2; bl[1][1] = t3;
            LDSM_X4(t0, t1, t2, t3, bl_addr + MT_STEP + koff);
            bl[2][0] = t0; bl[2][1] = t1; bl[3][0] = t2; bl[3][1] = t3;

            #pragma unroll
            for (int mt = 0; mt < 2; mt++)
                #pragma unroll
                for (int nt = 0; nt < 4; nt++) {
                    MMA_TF32(acc[mt][nt], ah[mt], bh[nt]);
                    MMA_TF32(acc[mt][nt], ah[mt], bl[nt]);
                    MMA_TF32(acc[mt][nt], al[mt], bh[nt]);
                }
        }
    }

    #pragma unroll
    for (int mt = 0; mt < 2; mt++)
        #pragma unroll
        for (int nt = 0; nt < 4; nt++) {
            int col = N0 + nt * 8 + tig * 2;
            int gc = c0 + col;
            int h = gc >> 6, d = gc & 63;
            float b0v = bias[gc], b1v = bias[gc + 1];
            #pragma unroll
            for (int hh = 0; hh < 2; hh++) {
                int gr = r0 + M0 + mt * 16 + g + hh * 8;
                if (gr >= ROWS_) continue;
                int b = gr / L_, l = gr % L_;
                float v0 = (acc[mt][nt][hh * 2 + 0] + b0v) * scale;
                float v1 = (acc[mt][nt][hh * 2 + 1] + b1v) * scale;
                float* dst = out + (((size_t)(b * H_ + h)) * L_ + l) * HD_ + d;
                dst[0] = v0;
                dst[1] = v1;
            }
        }
}

// ---------------------------------------------------------------------------
// Kernel 3: out = g_ao @ Wo^T + bo  (round-11 verbatim)
// ---------------------------------------------------------------------------
__global__ void __launch_bounds__(256, 2)
oproj_mma_kernel(const float* __restrict__ Wo,
                 const float* __restrict__ bo,
                 float* __restrict__ out)
{
    extern __shared__ uint32_t smem_u[];
    uint32_t* AH = smem_u;
    uint32_t* AL = AH + 128 * AST_;
    uint32_t* BH = AL + 128 * AST_;
    uint32_t* BL = BH + 64 * AST_;

    const int tid  = threadIdx.x;
    const int warp = tid >> 5;
    const int lane = tid & 31;
    const int g    = lane >> 2;
    const int tig  = lane & 3;
    const int warpM = warp & 3;
    const int warpN = warp >> 2;
    const int M0 = warpM * 32;
    const int N0 = warpN * 32;

    const int r0 = blockIdx.y * 128;
    const int c0 = blockIdx.x * 64;

    const int lm = tid >> 3;
    const int lk = (tid & 7) * 4;

    const int r8 = lane & 7;
    const int mi = lane >> 3;
    const int rowA = (mi & 1) * 8 + r8, kA = (mi >> 1) * 4;
    const int rowB = (mi >> 1) * 8 + r8, kB = (mi & 1) * 4;
    const uint32_t ah_addr = smem_u32(AH) + (((M0 + rowA) * AST_ + kA) << 2);
    const uint32_t al_addr = smem_u32(AL) + (((M0 + rowA) * AST_ + kA) << 2);
    const uint32_t bh_addr = smem_u32(BH) + (((N0 + rowB) * AST_ + kB) << 2);
    const uint32_t bl_addr = smem_u32(BL) + (((N0 + rowB) * AST_ + kB) << 2);
    const uint32_t MT_STEP = (16 * AST_) << 2;

    const float* xsrc[4];
    #pragma unroll
    for (int p = 0; p < 4; p++) {
        int gr = r0 + lm + p * 32;
        xsrc[p] = (gr < ROWS_) ? (g_ao + (size_t)gr * D_) : nullptr;
    }
    const float* wsrc0 = Wo + (size_t)(c0 + lm) * D_;
    const float* wsrc1 = Wo + (size_t)(c0 + lm + 32) * D_;

    float acc[2][4][4] = {};

    float4 xa[4], wb[2];
    #pragma unroll
    for (int p = 0; p < 4; p++) {
        xa[p] = make_float4(0.f, 0.f, 0.f, 0.f);
        if (xsrc[p]) xa[p] = *reinterpret_cast<const float4*>(xsrc[p] + lk);
    }
    wb[0] = *reinterpret_cast<const float4*>(wsrc0 + lk);
    wb[1] = *reinterpret_cast<const float4*>(wsrc1 + lk);

    for (int k0 = 0; k0 < D_; k0 += 32) {
        __syncthreads();
        #pragma unroll
        for (int p = 0; p < 4; p++) {
            uint4 h4, l4;
            split_tf32(xa[p].x, h4.x, l4.x);
            split_tf32(xa[p].y, h4.y, l4.y);
            split_tf32(xa[p].z, h4.z, l4.z);
            split_tf32(xa[p].w, h4.w, l4.w);
            int m = lm + p * 32;
            *reinterpret_cast<uint4*>(AH + m * AST_ + lk) = h4;
            *reinterpret_cast<uint4*>(AL + m * AST_ + lk) = l4;
        }
        #pragma unroll
        for (int p = 0; p < 2; p++) {
            uint4 h4, l4;
            split_tf32(wb[p].x, h4.x, l4.x);
            split_tf32(wb[p].y, h4.y, l4.y);
            split_tf32(wb[p].z, h4.z, l4.z);
            split_tf32(wb[p].w, h4.w, l4.w);
            int n = lm + p * 32;
            *reinterpret_cast<uint4*>(BH + n * AST_ + lk) = h4;
            *reinterpret_cast<uint4*>(BL + n * AST_ + lk) = l4;
        }
        __syncthreads();

        if (k0 + 32 < D_) {
            #pragma unroll
            for (int p = 0; p < 4; p++) {
                if (xsrc[p]) xa[p] = *reinterpret_cast<const float4*>(xsrc[p] + k0 + 32 + lk);
            }
            wb[0] = *reinterpret_cast<const float4*>(wsrc0 + k0 + 32 + lk);
            wb[1] = *reinterpret_cast<const float4*>(wsrc1 + k0 + 32 + lk);
        }

        #pragma unroll
        for (int ks = 0; ks < 4; ks++) {
            const uint32_t koff = (ks * 8) << 2;
            uint32_t ah[2][4], al[2][4], bh[4][2], bl[4][2];
            LDSM_X4(ah[0][0], ah[0][1], ah[0][2], ah[0][3], ah_addr + koff);
            LDSM_X4(ah[1][0], ah[1][1], ah[1][2], ah[1][3], ah_addr + MT_STEP + koff);
            LDSM_X4(al[0][0], al[0][1], al[0][2], al[0][3], al_addr + koff);
            LDSM_X4(al[1][0], al[1][1], al[1][2], al[1][3], al_addr + MT_STEP + koff);
            uint32_t t0, t1, t2, t3;
            LDSM_X4(t0, t1, t2, t3, bh_addr + koff);
            bh[0][0] = t0; bh[0][1] = t1; bh[1][0] = t2; bh[1][1] = t3;
            LDSM_X4(t0, t1, t2, t3, bh_addr + MT_STEP + koff);
            bh[2][0] = t0; bh[2][1] = t1; bh[3][0] = t2; bh[3][1] = t3;
            LDSM_X4(t0, t1, t2, t3, bl_addr + koff);
            bl[0][0] = t0; bl[0][1] = t1; bl[1][0] = t2; bl[1][1] = t3;
            LDSM_X4(t0, t1, t2, t3, bl_addr + MT_STEP + koff);
            bl[2][0] = t0; bl[2][1] = t1; bl[3][0] = t2; bl[3][1] = t3;

            #pragma unroll
            for (int mt = 0; mt < 2; mt++)
                #pragma unroll
                for (int nt = 0; nt < 4; nt++) {
                    MMA_TF32(acc[mt][nt], ah[mt], bh[nt]);
                    MMA_TF32(acc[mt][nt], ah[mt], bl[nt]);
                    MMA_TF32(acc[mt][nt], al[mt], bh[nt]);
                }
        }
    }

    #pragma unroll
    for (int mt = 0; mt < 2; mt++)
        #pragma unroll
        for (int nt = 0; nt < 4; nt++) {
            int gc = c0 + N0 + nt * 8 + tig * 2;
            float b0v = bo[gc], b1v = bo[gc + 1];
            #pragma unroll
            for (int hh = 0; hh < 2; hh++) {
                int gr = r0 + M0 + mt * 16 + g + hh * 8;
                if (gr >= ROWS_) continue;
                float* dst = out + (size_t)gr * D_ + gc;
                dst[0] = acc[mt][nt][hh * 2 + 0] + b0v;
                dst[1] = acc[mt][nt][hh * 2 + 1] + b1v;
            }
        }
}

// ---------------------------------------------------------------------------
// Kernel 2: flash attention — LPT grid (round-15) with V in SINGLE tf32
// (rna-rounded): PV = (Ph+Pl)·V̂h, 2 mma instead of 3. V-lo buffer unused.
// ---------------------------------------------------------------------------
__global__ void flash_mma_kernel(const int* __restrict__ node_indices,
                                 const unsigned char* __restrict__ key_pad,
                                 const unsigned char* __restrict__ node_pad)
{
    extern __shared__ uint32_t sm[];
    uint32_t* KH = sm;
    uint32_t* KL = KH + 64 * FST_;
    uint32_t* VH = KL + 64 * FST_;
    uint32_t* VL = VH + 64 * FST_;   // unused (kept for layout stability)
    uint32_t* PH = VL + 64 * FST_;
    uint32_t* PL = PH + 64 * FST_;
    int* clo = (int*)(PL + 64 * FST_);
    int* chi = clo + 64;

    const int bh = blockIdx.x;                    // 0..31
    const int b  = bh >> 3;
    const int h  = bh & 7;
    const int i0 = (15 - (int)blockIdx.y) * 64;   // heavy blocks first (LPT)
    const bool qleaf = (i0 < TK_);

    const int tid  = threadIdx.x;       // 128
    const int warp = tid >> 5;
    const int lane = tid & 31;
    const int g    = lane >> 2;
    const int tig  = lane & 3;
    const int wrow = warp * 16;

    const int lj = tid >> 4;            // 0..7
    const int lc = (tid & 15) * 4;      // 0,4,...,60

    #pragma unroll
    for (int p = 0; p < 8; p++) {
        int row = p * 8 + lj;
        int gi = i0 + row;
        float4 qv = make_float4(0.f, 0.f, 0.f, 0.f);
        if (gi < L_)
            qv = *reinterpret_cast<const float4*>(g_q + ((size_t)bh * L_ + gi) * HD_ + lc);
        uint4 h4, l4;
        split_tf32(qv.x, h4.x, l4.x);
        split_tf32(qv.y, h4.y, l4.y);
        split_tf32(qv.z, h4.z, l4.z);
        split_tf32(qv.w, h4.w, l4.w);
        *reinterpret_cast<uint4*>(PH + row * FST_ + lc) = h4;
        *reinterpret_cast<uint4*>(PL + row * FST_ + lc) = l4;
    }
    __syncthreads();

    uint32_t qh[8][4], ql[8][4];
    #pragma unroll
    for (int kk = 0; kk < 8; kk++) {
        int base0 = (wrow + g) * FST_ + kk * 8;
        int base1 = (wrow + 8 + g) * FST_ + kk * 8;
        qh[kk][0] = PH[base0 + tig];
        qh[kk][1] = PH[base1 + tig];
        qh[kk][2] = PH[base0 + tig + 4];
        qh[kk][3] = PH[base1 + tig + 4];
        ql[kk][0] = PL[base0 + tig];
        ql[kk][1] = PL[base1 + tig];
        ql[kk][2] = PL[base0 + tig + 4];
        ql[kk][3] = PL[base1 + tig + 4];
    }

    const int r0 = i0 + wrow + g;
    const int r1 = r0 + 8;
    int qlo0 = 0, qhi0 = 0, qloL0 = 0, qlo1 = 0, qhi1 = 0, qloL1 = 0;
    if (!qleaf) {
        int nq0 = min(r0 - TK_, NK_ - 1);
        qlo0 = node_indices[((size_t)bh * NK_ + nq0) * 2 + 0];
        qhi0 = node_indices[((size_t)bh * NK_ + nq0) * 2 + 1];
        qloL0 = (node_pad[b * NK_ + nq0] != 0) ? (1 << 28) : qlo0;
        int nq1 = min(r1 - TK_, NK_ - 1);
        qlo1 = node_indices[((size_t)bh * NK_ + nq1) * 2 + 0];
        qhi1 = node_indices[((size_t)bh * NK_ + nq1) * 2 + 1];
        qloL1 = (node_pad[b * NK_ + nq1] != 0) ? (1 << 28) : qlo1;
    }

    float m0 = -1e30f, m1 = -1e30f, lsum0 = 0.f, lsum1 = 0.f;
    float acc[8][4] = {};

    const int ntiles = qleaf ? 8 : (9 + (i0 - TK_) / 64);
    for (int jt = 0; jt < ntiles; jt++) {
        const bool nodetile = (jt >= 8);
        const int j0 = nodetile ? TK_ + (jt - 8) * 64 : jt * 64;

        __syncthreads();
        #pragma unroll
        for (int p = 0; p < 8; p++) {
            int row = p * 8 + lj;
            int gj = j0 + row;
            float4 kv = make_float4(0.f, 0.f, 0.f, 0.f);
            if (gj < L_)
                kv = *reinterpret_cast<const float4*>(g_k + ((size_t)bh * L_ + gj) * HD_ + lc);
            uint4 h4, l4;
            split_tf32(kv.x, h4.x, l4.x);
            split_tf32(kv.y, h4.y, l4.y);
            split_tf32(kv.z, h4.z, l4.z);
            split_tf32(kv.w, h4.w, l4.w);
            *reinterpret_cast<uint4*>(KH + row * FST_ + lc) = h4;
            *reinterpret_cast<uint4*>(KL + row * FST_ + lc) = l4;
        }
        // ---- V tile: single rna tf32 (error <= 2^-12 rel) ----
        #pragma unroll
        for (int p = 0; p < 8; p++) {
            int row = p * 8 + lj;
            int gj = j0 + row;
            float4 vv = make_float4(0.f, 0.f, 0.f, 0.f);
            if (gj < L_)
                vv = *reinterpret_cast<const float4*>(g_v + ((size_t)bh * L_ + gj) * HD_ + lc);
            uint4 h4;
            h4.x = cvt_tf32(vv.x);
            h4.y = cvt_tf32(vv.y);
            h4.z = cvt_tf32(vv.z);
            h4.w = cvt_tf32(vv.w);
            *reinterpret_cast<uint4*>(VH + row * FST_ + lc) = h4;
        }
        if (nodetile && tid < 64) {
            int gj = j0 + tid;
            int nj = gj - TK_;
            int lo = (1 << 28), hi = -(1 << 28);
            if (nj < NK_ && gj < L_ && node_pad[b * NK_ + nj] == 0) {
                lo = node_indices[((size_t)bh * NK_ + nj) * 2 + 0];
                hi = node_indices[((size_t)bh * NK_ + nj) * 2 + 1];
            }
            clo[tid] = lo;
            chi[tid] = hi;
        }
        __syncthreads();

        float s[8][4];
        #pragma unroll
        for (int nf = 0; nf < 8; nf++) {
            s[nf][0] = 0.f; s[nf][1] = 0.f; s[nf][2] = 0.f; s[nf][3] = 0.f;
        }
        for (int kk = 0; kk < 8; kk++) {
            #pragma unroll
            for (int nf = 0; nf < 8; nf++) {
                int nb = (nf * 8 + g) * FST_ + kk * 8;
                uint32_t bhv[2] = {KH[nb + tig], KH[nb + tig + 4]};
                uint32_t blv[2] = {KL[nb + tig], KL[nb + tig + 4]};
                MMA_TF32(s[nf], qh[kk], bhv);
                MMA_TF32(s[nf], qh[kk], blv);
                MMA_TF32(s[nf], ql[kk], bhv);
            }
        }

        if (qleaf) {
            #pragma unroll
            for (int nf = 0; nf < 8; nf++) {
                int gj = j0 + nf * 8 + 2 * tig;
                if (key_pad[b * TK_ + gj])     { s[nf][0] = -1e30f; s[nf][2] = -1e30f; }
                if (key_pad[b * TK_ + gj + 1]) { s[nf][1] = -1e30f; s[nf][3] = -1e30f; }
            }
        } else if (!nodetile) {
            #pragma unroll
            for (int nf = 0; nf < 8; nf++) {
                int gj = j0 + nf * 8 + 2 * tig;
                bool kp0 = (key_pad[b * TK_ + gj] != 0);
                bool kp1 = (key_pad[b * TK_ + gj + 1] != 0);
                if (!(gj >= qloL0 && gj <= qhi0 && !kp0))             s[nf][0] = -1e30f;
                if (!((gj + 1) >= qloL0 && (gj + 1) <= qhi0 && !kp1)) s[nf][1] = -1e30f;
                if (!(gj >= qloL1 && gj <= qhi1 && !kp0))             s[nf][2] = -1e30f;
                if (!((gj + 1) >= qloL1 && (gj + 1) <= qhi1 && !kp1)) s[nf][3] = -1e30f;
            }
        } else {
            int nq0 = r0 - TK_, nq1 = r1 - TK_;
            #pragma unroll
            for (int nf = 0; nf < 8; nf++) {
                int cj = nf * 8 + 2 * tig;
                int nj0 = j0 + cj - TK_;
                int lo20 = clo[cj],     hi20 = chi[cj];
                int lo21 = clo[cj + 1], hi21 = chi[cj + 1];
                if (!(nj0 <= nq0 && max(qlo0, lo20) <= min(qhi0, hi20)))     s[nf][0] = -1e30f;
                if (!(nj0 + 1 <= nq0 && max(qlo0, lo21) <= min(qhi0, hi21))) s[nf][1] = -1e30f;
                if (!(nj0 <= nq1 && max(qlo1, lo20) <= min(qhi1, hi20)))     s[nf][2] = -1e30f;
                if (!(nj0 + 1 <= nq1 && max(qlo1, lo21) <= min(qhi1, hi21))) s[nf][3] = -1e30f;
            }
        }

        float tm0 = -1e30f, tm1 = -1e30f;
        #pragma unroll
        for (int nf = 0; nf < 8; nf++) {
            tm0 = fmaxf(tm0, fmaxf(s[nf][0], s[nf][1]));
            tm1 = fmaxf(tm1, fmaxf(s[nf][2], s[nf][3]));
        }
        tm0 = fmaxf(tm0, __shfl_xor_sync(0xffffffffu, tm0, 1));
        tm0 = fmaxf(tm0, __shfl_xor_sync(0xffffffffu, tm0, 2));
        tm1 = fmaxf(tm1, __shfl_xor_sync(0xffffffffu, tm1, 1));
        tm1 = fmaxf(tm1, __shfl_xor_sync(0xffffffffu, tm1, 2));

        float mn0 = fmaxf(m0, tm0);
        float mn1 = fmaxf(m1, tm1);
        float a0 = __expf(m0 - mn0);
        float a1 = __expf(m1 - mn1);
        m0 = mn0; m1 = mn1;
        float sb0 = fmaxf(mn0, -1e20f);
        float sb1 = fmaxf(mn1, -1e20f);

        float rs0 = 0.f, rs1 = 0.f;
        #pragma unroll
        for (int nf = 0; nf < 8; nf++) {
            s[nf][0] = __expf(s[nf][0] - sb0);
            s[nf][1] = __expf(s[nf][1] - sb0);
            s[nf][2] = __expf(s[nf][2] - sb1);
            s[nf][3] = __expf(s[nf][3] - sb1);
            rs0 += s[nf][0] + s[nf][1];
            rs1 += s[nf][2] + s[nf][3];
        }
        rs0 += __shfl_xor_sync(0xffffffffu, rs0, 1);
        rs0 += __shfl_xor_sync(0xffffffffu, rs0, 2);
        rs1 += __shfl_xor_sync(0xffffffffu, rs1, 1);
        rs1 += __shfl_xor_sync(0xffffffffu, rs1, 2);
        lsum0 = lsum0 * a0 + rs0;
        lsum1 = lsum1 * a1 + rs1;
        #pragma unroll
        for (int nf = 0; nf < 8; nf++) {
            acc[nf][0] *= a0; acc[nf][1] *= a0;
            acc[nf][2] *= a1; acc[nf][3] *= a1;
        }

        #pragma unroll
        for (int nf = 0; nf < 8; nf++) {
            int bg  = (wrow + g) * FST_ + nf * 8 + 2 * tig;
            int bg8 = (wrow + 8 + g) * FST_ + nf * 8 + 2 * tig;
            uint32_t h0, l0, h1, l1;
            split_tf32(s[nf][0], h0, l0);
            split_tf32(s[nf][1], h1, l1);
            *reinterpret_cast<uint2*>(PH + bg) = make_uint2(h0, h1);
            *reinterpret_cast<uint2*>(PL + bg) = make_uint2(l0, l1);
            split_tf32(s[nf][2], h0, l0);
            split_tf32(s[nf][3], h1, l1);
            *reinterpret_cast<uint2*>(PH + bg8) = make_uint2(h0, h1);
            *reinterpret_cast<uint2*>(PL + bg8) = make_uint2(l0, l1);
        }
        __syncwarp();

        // ---- acc += (Ph + Pl) . V̂h   (2 mma per fragment) ----
        for (int kk = 0; kk < 8; kk++) {
            int base0 = (wrow + g) * FST_ + kk * 8;
            int base1 = (wrow + 8 + g) * FST_ + kk * 8;
            uint32_t ah[4] = {PH[base0 + tig], PH[base1 + tig],
                              PH[base0 + tig + 4], PH[base1 + tig + 4]};
            uint32_t al[4] = {PL[base0 + tig], PL[base1 + tig],
                              PL[base0 + tig + 4], PL[base1 + tig + 4]};
            #pragma unroll
            for (int nf = 0; nf < 8; nf++) {
                int vb0 = (kk * 8 + tig) * FST_ + nf * 8 + g;
                int vb1 = (kk * 8 + tig + 4) * FST_ + nf * 8 + g;
                uint32_t bhv[2] = {VH[vb0], VH[vb1]};
                MMA_TF32(acc[nf], ah, bhv);
                MMA_TF32(acc[nf], al, bhv);
            }
        }
    }

    float inv0 = 1.0f / lsum0;
    float inv1 = 1.0f / lsum1;
    #pragma unroll
    for (int nf = 0; nf < 8; nf++) {
        int d0 = nf * 8 + 2 * tig;
        if (r0 < L_) {
            float2 v = make_float2(acc[nf][0] * inv0, acc[nf][1] * inv0);
            *reinterpret_cast<float2*>(g_ao + ((size_t)(b * L_ + r0)) * D_ + h * HD_ + d0) = v;
        }
        if (r1 < L_) {
            float2 v = make_float2(acc[nf][2] * inv1, acc[nf][3] * inv1);
            *reinterpret_cast<float2*>(g_ao + ((size_t)(b * L_ + r1)) * D_ + h * HD_ + d0) = v;
        }
    }
}

// ---------------------------------------------------------------------------
extern "C" void kernel_launch(void* const* d_in, const int* in_sizes, int n_in,
                              void* d_out, int out_size)
{
    const float* leaves = (const float*)d_in[0];
    const float* nodes  = (const float*)d_in[1];
    const float* Wq     = (const float*)d_in[2];
    const float* Wk     = (const float*)d_in[3];
    const float* Wv     = (const float*)d_in[4];
    const float* Wo     = (const float*)d_in[5];
    const float* bq     = (const float*)d_in[6];
    const float* bk     = (const float*)d_in[7];
    const float* bv     = (const float*)d_in[8];
    const float* bo     = (const float*)d_in[9];
    const int*   node_indices = (const int*)d_in[10];
    const unsigned char* key_pad  = (const unsigned char*)d_in[11];
    const unsigned char* node_pad = (const unsigned char*)d_in[12];
    float* out = (float*)d_out;

    static int smem_set = 0;
    if (!smem_set) {
        cudaFuncSetAttribute(flash_mma_kernel,
                             cudaFuncAttributeMaxDynamicSharedMemorySize,
                             FLASH_SMEM);
        cudaFuncSetAttribute(qkv_mma_kernel,
                             cudaFuncAttributeMaxDynamicSharedMemorySize,
                             GEMM_SMEM_BYTES);
        cudaFuncSetAttribute(oproj_mma_kernel,
                             cudaFuncAttributeMaxDynamicSharedMemorySize,
                             GEMM_SMEM_BYTES);
        smem_set = 1;
    }

    qkv_mma_kernel<<<dim3(8, 32, 3), 256, GEMM_SMEM_BYTES>>>(
        leaves, nodes, Wq, Wk, Wv, bq, bk, bv);
    flash_mma_kernel<<<dim3(32, 16), 128, FLASH_SMEM>>>(node_indices, key_pad, node_pad);
    oproj_mma_kernel<<<dim3(8, 32), 256, GEMM_SMEM_BYTES>>>(Wo, bo, out);
}

// round 17
// speedup vs baseline: 1.2963x; 1.0439x over previous
#include <cuda_runtime.h>
#include <cstdint>

#define B_    4
#define H_    8
#define TK_   512
#define NK_   511
#define L_    1023
#define D_    512
#define HD_   64
#define BH_   32
#define ROWS_ 4092          // B_*L_

// Scratch (static __device__ — no allocations allowed)
__device__ float g_q[B_*H_*L_*HD_];
__device__ float g_k[B_*H_*L_*HD_];
__device__ float g_v[B_*H_*L_*HD_];
__device__ float g_ao[B_*L_*D_];            // attention output, (B,L, H*HD)

// ---------------------------------------------------------------------------
// tf32 helpers
// ---------------------------------------------------------------------------
__device__ __forceinline__ void split_tf32(float x, uint32_t& hi, uint32_t& lo)
{
    float h, l2;
    asm("cvt.rna.tf32.f32 %0, %1;" : "=f"(h) : "f"(x));
    float l = x - h;
    asm("cvt.rna.tf32.f32 %0, %1;" : "=f"(l2) : "f"(l));
    hi = __float_as_uint(h);
    lo = __float_as_uint(l2);
}

__device__ __forceinline__ uint32_t cvt_tf32(float x)
{
    float h;
    asm("cvt.rna.tf32.f32 %0, %1;" : "=f"(h) : "f"(x));
    return __float_as_uint(h);
}

#define MMA_TF32(d, a, b)                                                     \
    asm volatile(                                                             \
        "mma.sync.aligned.m16n8k8.row.col.f32.tf32.tf32.f32 "                 \
        "{%0,%1,%2,%3}, {%4,%5,%6,%7}, {%8,%9}, {%0,%1,%2,%3};"               \
        : "+f"((d)[0]), "+f"((d)[1]), "+f"((d)[2]), "+f"((d)[3])              \
        : "r"((a)[0]), "r"((a)[1]), "r"((a)[2]), "r"((a)[3]),                 \
          "r"((b)[0]), "r"((b)[1]))

// ldmatrix x4: 4 8x8 b16 matrices; register layout == tf32 mma fragment.
#define LDSM_X4(R0, R1, R2, R3, ADDR)                                         \
    asm volatile("ldmatrix.sync.aligned.m8n8.x4.shared.b16 {%0,%1,%2,%3}, [%4];" \
        : "=r"(R0), "=r"(R1), "=r"(R2), "=r"(R3) : "r"(ADDR))

__device__ __forceinline__ uint32_t smem_u32(const void* p)
{
    return (uint32_t)__cvta_generic_to_shared(p);
}

// GEMM kernels: k-chunk = 32 -> stride 36
#define AST_ 36
#define GEMM_SMEM_BYTES ((2*128*AST_ + 2*64*AST_) * 4)   // 55296
// Flash tiles hold full k=64 -> stride 68
#define FST_ 68
#define FLASH_SMEM (6*64*FST_*4 + 2*64*4)                // 104960

// ---------------------------------------------------------------------------
// Kernel 1: fused QKV projection (round-11 verbatim — proven)
// ---------------------------------------------------------------------------
__global__ void __launch_bounds__(256, 2)
qkv_mma_kernel(const float* __restrict__ leaves,
               const float* __restrict__ nodes,
               const float* __restrict__ Wq,
               const float* __restrict__ Wk,
               const float* __restrict__ Wv,
               const float* __restrict__ bq,
               const float* __restrict__ bk,
               const float* __restrict__ bv)
{
    const int z = blockIdx.z;
    const float* W    = (z == 0) ? Wq : (z == 1) ? Wk : Wv;
    const float* bias = (z == 0) ? bq : (z == 1) ? bk : bv;
    float* out        = (z == 0) ? g_q : (z == 1) ? g_k : g_v;
    const float scale = (z == 0) ? 0.125f : 1.0f;

    extern __shared__ uint32_t smem_u[];
    uint32_t* AH = smem_u;
    uint32_t* AL = AH + 128 * AST_;
    uint32_t* BH = AL + 128 * AST_;
    uint32_t* BL = BH + 64 * AST_;

    const int tid  = threadIdx.x;
    const int warp = tid >> 5;
    const int lane = tid & 31;
    const int g    = lane >> 2;
    const int tig  = lane & 3;
    const int warpM = warp & 3;
    const int warpN = warp >> 2;
    const int M0 = warpM * 32;
    const int N0 = warpN * 32;

    const int r0 = blockIdx.y * 128;
    const int c0 = blockIdx.x * 64;

    const int lm = tid >> 3;
    const int lk = (tid & 7) * 4;

    const int r8 = lane & 7;
    const int mi = lane >> 3;
    const int rowA = (mi & 1) * 8 + r8, kA = (mi >> 1) * 4;
    const int rowB = (mi >> 1) * 8 + r8, kB = (mi & 1) * 4;
    const uint32_t ah_addr = smem_u32(AH) + (((M0 + rowA) * AST_ + kA) << 2);
    const uint32_t al_addr = smem_u32(AL) + (((M0 + rowA) * AST_ + kA) << 2);
    const uint32_t bh_addr = smem_u32(BH) + (((N0 + rowB) * AST_ + kB) << 2);
    const uint32_t bl_addr = smem_u32(BL) + (((N0 + rowB) * AST_ + kB) << 2);
    const uint32_t MT_STEP = (16 * AST_) << 2;

    const float* xsrc[4];
    #pragma unroll
    for (int p = 0; p < 4; p++) {
        int gr = r0 + lm + p * 32;
        if (gr < ROWS_) {
            int b = gr / L_, t = gr % L_;
            xsrc[p] = (t < TK_) ? (leaves + ((size_t)(b * TK_ + t)) * D_)
                                : (nodes  + ((size_t)(b * NK_ + (t - TK_))) * D_);
        } else xsrc[p] = nullptr;
    }
    const float* wsrc0 = W + (size_t)(c0 + lm) * D_;
    const float* wsrc1 = W + (size_t)(c0 + lm + 32) * D_;

    float acc[2][4][4] = {};

    float4 xa[4], wb[2];
    #pragma unroll
    for (int p = 0; p < 4; p++) {
        xa[p] = make_float4(0.f, 0.f, 0.f, 0.f);
        if (xsrc[p]) xa[p] = *reinterpret_cast<const float4*>(xsrc[p] + lk);
    }
    wb[0] = *reinterpret_cast<const float4*>(wsrc0 + lk);
    wb[1] = *reinterpret_cast<const float4*>(wsrc1 + lk);

    for (int k0 = 0; k0 < D_; k0 += 32) {
        __syncthreads();
        #pragma unroll
        for (int p = 0; p < 4; p++) {
            uint4 h4, l4;
            split_tf32(xa[p].x, h4.x, l4.x);
            split_tf32(xa[p].y, h4.y, l4.y);
            split_tf32(xa[p].z, h4.z, l4.z);
            split_tf32(xa[p].w, h4.w, l4.w);
            int m = lm + p * 32;
            *reinterpret_cast<uint4*>(AH + m * AST_ + lk) = h4;
            *reinterpret_cast<uint4*>(AL + m * AST_ + lk) = l4;
        }
        #pragma unroll
        for (int p = 0; p < 2; p++) {
            uint4 h4, l4;
            split_tf32(wb[p].x, h4.x, l4.x);
            split_tf32(wb[p].y, h4.y, l4.y);
            split_tf32(wb[p].z, h4.z, l4.z);
            split_tf32(wb[p].w, h4.w, l4.w);
            int n = lm + p * 32;
            *reinterpret_cast<uint4*>(BH + n * AST_ + lk) = h4;
            *reinterpret_cast<uint4*>(BL + n * AST_ + lk) = l4;
        }
        __syncthreads();

        if (k0 + 32 < D_) {
            #pragma unroll
            for (int p = 0; p < 4; p++) {
                if (xsrc[p]) xa[p] = *reinterpret_cast<const float4*>(xsrc[p] + k0 + 32 + lk);
            }
            wb[0] = *reinterpret_cast<const float4*>(wsrc0 + k0 + 32 + lk);
            wb[1] = *reinterpret_cast<const float4*>(wsrc1 + k0 + 32 + lk);
        }

        #pragma unroll
        for (int ks = 0; ks < 4; ks++) {
            const uint32_t koff = (ks * 8) << 2;
            uint32_t ah[2][4], al[2][4], bh[4][2], bl[4][2];
            LDSM_X4(ah[0][0], ah[0][1], ah[0][2], ah[0][3], ah_addr + koff);
            LDSM_X4(ah[1][0], ah[1][1], ah[1][2], ah[1][3], ah_addr + MT_STEP + koff);
            LDSM_X4(al[0][0], al[0][1], al[0][2], al[0][3], al_addr + koff);
            LDSM_X4(al[1][0], al[1][1], al[1][2], al[1][3], al_addr + MT_STEP + koff);
            uint32_t t0, t1, t2, t3;
            LDSM_X4(t0, t1, t2, t3, bh_addr + koff);
            bh[0][0] = t0; bh[0][1] = t1; bh[1][0] = t2; bh[1][1] = t3;
            LDSM_X4(t0, t1, t2, t3, bh_addr + MT_STEP + koff);
            bh[2][0] = t0; bh[2][1] = t1; bh[3][0] = t2; bh[3][1] = t3;
            LDSM_X4(t0, t1, t2, t3, bl_addr + koff);
            bl[0][0] = t0; bl[0][1] = t1; bl[1][0] = t2; bl[1][1] = t3;
            LDSM_X4(t0, t1, t2, t3, bl_addr + MT_STEP + koff);
            bl[2][0] = t0; bl[2][1] = t1; bl[3][0] = t2; bl[3][1] = t3;

            #pragma unroll
            for (int mt = 0; mt < 2; mt++)
                #pragma unroll
                for (int nt = 0; nt < 4; nt++) {
                    MMA_TF32(acc[mt][nt], ah[mt], bh[nt]);
                    MMA_TF32(acc[mt][nt], ah[mt], bl[nt]);
                    MMA_TF32(acc[mt][nt], al[mt], bh[nt]);
                }
        }
    }

    #pragma unroll
    for (int mt = 0; mt < 2; mt++)
        #pragma unroll
        for (int nt = 0; nt < 4; nt++) {
            int col = N0 + nt * 8 + tig * 2;
            int gc = c0 + col;
            int h = gc >> 6, d = gc & 63;
            float b0v = bias[gc], b1v = bias[gc + 1];
            #pragma unroll
            for (int hh = 0; hh < 2; hh++) {
                int gr = r0 + M0 + mt * 16 + g + hh * 8;
                if (gr >= ROWS_) continue;
                int b = gr / L_, l = gr % L_;
                float v0 = (acc[mt][nt][hh * 2 + 0] + b0v) * scale;
                float v1 = (acc[mt][nt][hh * 2 + 1] + b1v) * scale;
                float* dst = out + (((size_t)(b * H_ + h)) * L_ + l) * HD_ + d;
                dst[0] = v0;
                dst[1] = v1;
            }
        }
}

// ---------------------------------------------------------------------------
// Kernel 3: out = g_ao @ Wo^T + bo  (round-11 verbatim)
// ---------------------------------------------------------------------------
__global__ void __launch_bounds__(256, 2)
oproj_mma_kernel(const float* __restrict__ Wo,
                 const float* __restrict__ bo,
                 float* __restrict__ out)
{
    extern __shared__ uint32_t smem_u[];
    uint32_t* AH = smem_u;
    uint32_t* AL = AH + 128 * AST_;
    uint32_t* BH = AL + 128 * AST_;
    uint32_t* BL = BH + 64 * AST_;

    const int tid  = threadIdx.x;
    const int warp = tid >> 5;
    const int lane = tid & 31;
    const int g    = lane >> 2;
    const int tig  = lane & 3;
    const int warpM = warp & 3;
    const int warpN = warp >> 2;
    const int M0 = warpM * 32;
    const int N0 = warpN * 32;

    const int r0 = blockIdx.y * 128;
    const int c0 = blockIdx.x * 64;

    const int lm = tid >> 3;
    const int lk = (tid & 7) * 4;

    const int r8 = lane & 7;
    const int mi = lane >> 3;
    const int rowA = (mi & 1) * 8 + r8, kA = (mi >> 1) * 4;
    const int rowB = (mi >> 1) * 8 + r8, kB = (mi & 1) * 4;
    const uint32_t ah_addr = smem_u32(AH) + (((M0 + rowA) * AST_ + kA) << 2);
    const uint32_t al_addr = smem_u32(AL) + (((M0 + rowA) * AST_ + kA) << 2);
    const uint32_t bh_addr = smem_u32(BH) + (((N0 + rowB) * AST_ + kB) << 2);
    const uint32_t bl_addr = smem_u32(BL) + (((N0 + rowB) * AST_ + kB) << 2);
    const uint32_t MT_STEP = (16 * AST_) << 2;

    const float* xsrc[4];
    #pragma unroll
    for (int p = 0; p < 4; p++) {
        int gr = r0 + lm + p * 32;
        xsrc[p] = (gr < ROWS_) ? (g_ao + (size_t)gr * D_) : nullptr;
    }
    const float* wsrc0 = Wo + (size_t)(c0 + lm) * D_;
    const float* wsrc1 = Wo + (size_t)(c0 + lm + 32) * D_;

    float acc[2][4][4] = {};

    float4 xa[4], wb[2];
    #pragma unroll
    for (int p = 0; p < 4; p++) {
        xa[p] = make_float4(0.f, 0.f, 0.f, 0.f);
        if (xsrc[p]) xa[p] = *reinterpret_cast<const float4*>(xsrc[p] + lk);
    }
    wb[0] = *reinterpret_cast<const float4*>(wsrc0 + lk);
    wb[1] = *reinterpret_cast<const float4*>(wsrc1 + lk);

    for (int k0 = 0; k0 < D_; k0 += 32) {
        __syncthreads();
        #pragma unroll
        for (int p = 0; p < 4; p++) {
            uint4 h4, l4;
            split_tf32(xa[p].x, h4.x, l4.x);
            split_tf32(xa[p].y, h4.y, l4.y);
            split_tf32(xa[p].z, h4.z, l4.z);
            split_tf32(xa[p].w, h4.w, l4.w);
            int m = lm + p * 32;
            *reinterpret_cast<uint4*>(AH + m * AST_ + lk) = h4;
            *reinterpret_cast<uint4*>(AL + m * AST_ + lk) = l4;
        }
        #pragma unroll
        for (int p = 0; p < 2; p++) {
            uint4 h4, l4;
            split_tf32(wb[p].x, h4.x, l4.x);
            split_tf32(wb[p].y, h4.y, l4.y);
            split_tf32(wb[p].z, h4.z, l4.z);
            split_tf32(wb[p].w, h4.w, l4.w);
            int n = lm + p * 32;
            *reinterpret_cast<uint4*>(BH + n * AST_ + lk) = h4;
            *reinterpret_cast<uint4*>(BL + n * AST_ + lk) = l4;
        }
        __syncthreads();

        if (k0 + 32 < D_) {
            #pragma unroll
            for (int p = 0; p < 4; p++) {
                if (xsrc[p]) xa[p] = *reinterpret_cast<const float4*>(xsrc[p] + k0 + 32 + lk);
            }
            wb[0] = *reinterpret_cast<const float4*>(wsrc0 + k0 + 32 + lk);
            wb[1] = *reinterpret_cast<const float4*>(wsrc1 + k0 + 32 + lk);
        }

        #pragma unroll
        for (int ks = 0; ks < 4; ks++) {
            const uint32_t koff = (ks * 8) << 2;
            uint32_t ah[2][4], al[2][4], bh[4][2], bl[4][2];
            LDSM_X4(ah[0][0], ah[0][1], ah[0][2], ah[0][3], ah_addr + koff);
            LDSM_X4(ah[1][0], ah[1][1], ah[1][2], ah[1][3], ah_addr + MT_STEP + koff);
            LDSM_X4(al[0][0], al[0][1], al[0][2], al[0][3], al_addr + koff);
            LDSM_X4(al[1][0], al[1][1], al[1][2], al[1][3], al_addr + MT_STEP + koff);
            uint32_t t0, t1, t2, t3;
            LDSM_X4(t0, t1, t2, t3, bh_addr + koff);
            bh[0][0] = t0; bh[0][1] = t1; bh[1][0] = t2; bh[1][1] = t3;
            LDSM_X4(t0, t1, t2, t3, bh_addr + MT_STEP + koff);
            bh[2][0] = t0; bh[2][1] = t1; bh[3][0] = t2; bh[3][1] = t3;
            LDSM_X4(t0, t1, t2, t3, bl_addr + koff);
            bl[0][0] = t0; bl[0][1] = t1; bl[1][0] = t2; bl[1][1] = t3;
            LDSM_X4(t0, t1, t2, t3, bl_addr + MT_STEP + koff);
            bl[2][0] = t0; bl[2][1] = t1; bl[3][0] = t2; bl[3][1] = t3;

            #pragma unroll
            for (int mt = 0; mt < 2; mt++)
                #pragma unroll
                for (int nt = 0; nt < 4; nt++) {
                    MMA_TF32(acc[mt][nt], ah[mt], bh[nt]);
                    MMA_TF32(acc[mt][nt], ah[mt], bl[nt]);
                    MMA_TF32(acc[mt][nt], al[mt], bh[nt]);
                }
        }
    }

    #pragma unroll
    for (int mt = 0; mt < 2; mt++)
        #pragma unroll
        for (int nt = 0; nt < 4; nt++) {
            int gc = c0 + N0 + nt * 8 + tig * 2;
            float b0v = bo[gc], b1v = bo[gc + 1];
            #pragma unroll
            for (int hh = 0; hh < 2; hh++) {
                int gr = r0 + M0 + mt * 16 + g + hh * 8;
                if (gr >= ROWS_) continue;
                float* dst = out + (size_t)gr * D_ + gc;
                dst[0] = acc[mt][nt][hh * 2 + 0] + b0v;
                dst[1] = acc[mt][nt][hh * 2 + 1] + b1v;
            }
        }
}

// ---------------------------------------------------------------------------
// Kernel 2: flash attention — LPT grid; V single-tf32 (round-16 proven) and
// now K single-tf32 too: S = (Qh+Ql)·K̂h (2 mma), PV = (Ph+Pl)·V̂h (2 mma).
// ---------------------------------------------------------------------------
__global__ void flash_mma_kernel(const int* __restrict__ node_indices,
                                 const unsigned char* __restrict__ key_pad,
                                 const unsigned char* __restrict__ node_pad)
{
    extern __shared__ uint32_t sm[];
    uint32_t* KH = sm;
    uint32_t* KL = KH + 64 * FST_;   // unused (layout stability)
    uint32_t* VH = KL + 64 * FST_;
    uint32_t* VL = VH + 64 * FST_;   // unused (layout stability)
    uint32_t* PH = VL + 64 * FST_;
    uint32_t* PL = PH + 64 * FST_;
    int* clo = (int*)(PL + 64 * FST_);
    int* chi = clo + 64;

    const int bh = blockIdx.x;                    // 0..31
    const int b  = bh >> 3;
    const int h  = bh & 7;
    const int i0 = (15 - (int)blockIdx.y) * 64;   // heavy blocks first (LPT)
    const bool qleaf = (i0 < TK_);

    const int tid  = threadIdx.x;       // 128
    const int warp = tid >> 5;
    const int lane = tid & 31;
    const int g    = lane >> 2;
    const int tig  = lane & 3;
    const int wrow = warp * 16;

    const int lj = tid >> 4;            // 0..7
    const int lc = (tid & 15) * 4;      // 0,4,...,60

    #pragma unroll
    for (int p = 0; p < 8; p++) {
        int row = p * 8 + lj;
        int gi = i0 + row;
        float4 qv = make_float4(0.f, 0.f, 0.f, 0.f);
        if (gi < L_)
            qv = *reinterpret_cast<const float4*>(g_q + ((size_t)bh * L_ + gi) * HD_ + lc);
        uint4 h4, l4;
        split_tf32(qv.x, h4.x, l4.x);
        split_tf32(qv.y, h4.y, l4.y);
        split_tf32(qv.z, h4.z, l4.z);
        split_tf32(qv.w, h4.w, l4.w);
        *reinterpret_cast<uint4*>(PH + row * FST_ + lc) = h4;
        *reinterpret_cast<uint4*>(PL + row * FST_ + lc) = l4;
    }
    __syncthreads();

    uint32_t qh[8][4], ql[8][4];
    #pragma unroll
    for (int kk = 0; kk < 8; kk++) {
        int base0 = (wrow + g) * FST_ + kk * 8;
        int base1 = (wrow + 8 + g) * FST_ + kk * 8;
        qh[kk][0] = PH[base0 + tig];
        qh[kk][1] = PH[base1 + tig];
        qh[kk][2] = PH[base0 + tig + 4];
        qh[kk][3] = PH[base1 + tig + 4];
        ql[kk][0] = PL[base0 + tig];
        ql[kk][1] = PL[base1 + tig];
        ql[kk][2] = PL[base0 + tig + 4];
        ql[kk][3] = PL[base1 + tig + 4];
    }

    const int r0 = i0 + wrow + g;
    const int r1 = r0 + 8;
    int qlo0 = 0, qhi0 = 0, qloL0 = 0, qlo1 = 0, qhi1 = 0, qloL1 = 0;
    if (!qleaf) {
        int nq0 = min(r0 - TK_, NK_ - 1);
        qlo0 = node_indices[((size_t)bh * NK_ + nq0) * 2 + 0];
        qhi0 = node_indices[((size_t)bh * NK_ + nq0) * 2 + 1];
        qloL0 = (node_pad[b * NK_ + nq0] != 0) ? (1 << 28) : qlo0;
        int nq1 = min(r1 - TK_, NK_ - 1);
        qlo1 = node_indices[((size_t)bh * NK_ + nq1) * 2 + 0];
        qhi1 = node_indices[((size_t)bh * NK_ + nq1) * 2 + 1];
        qloL1 = (node_pad[b * NK_ + nq1] != 0) ? (1 << 28) : qlo1;
    }

    float m0 = -1e30f, m1 = -1e30f, lsum0 = 0.f, lsum1 = 0.f;
    float acc[8][4] = {};

    const int ntiles = qleaf ? 8 : (9 + (i0 - TK_) / 64);
    for (int jt = 0; jt < ntiles; jt++) {
        const bool nodetile = (jt >= 8);
        const int j0 = nodetile ? TK_ + (jt - 8) * 64 : jt * 64;

        __syncthreads();
        // ---- K tile: single rna tf32 ----
        #pragma unroll
        for (int p = 0; p < 8; p++) {
            int row = p * 8 + lj;
            int gj = j0 + row;
            float4 kv = make_float4(0.f, 0.f, 0.f, 0.f);
            if (gj < L_)
                kv = *reinterpret_cast<const float4*>(g_k + ((size_t)bh * L_ + gj) * HD_ + lc);
            uint4 h4;
            h4.x = cvt_tf32(kv.x);
            h4.y = cvt_tf32(kv.y);
            h4.z = cvt_tf32(kv.z);
            h4.w = cvt_tf32(kv.w);
            *reinterpret_cast<uint4*>(KH + row * FST_ + lc) = h4;
        }
        // ---- V tile: single rna tf32 ----
        #pragma unroll
        for (int p = 0; p < 8; p++) {
            int row = p * 8 + lj;
            int gj = j0 + row;
            float4 vv = make_float4(0.f, 0.f, 0.f, 0.f);
            if (gj < L_)
                vv = *reinterpret_cast<const float4*>(g_v + ((size_t)bh * L_ + gj) * HD_ + lc);
            uint4 h4;
            h4.x = cvt_tf32(vv.x);
            h4.y = cvt_tf32(vv.y);
            h4.z = cvt_tf32(vv.z);
            h4.w = cvt_tf32(vv.w);
            *reinterpret_cast<uint4*>(VH + row * FST_ + lc) = h4;
        }
        if (nodetile && tid < 64) {
            int gj = j0 + tid;
            int nj = gj - TK_;
            int lo = (1 << 28), hi = -(1 << 28);
            if (nj < NK_ && gj < L_ && node_pad[b * NK_ + nj] == 0) {
                lo = node_indices[((size_t)bh * NK_ + nj) * 2 + 0];
                hi = node_indices[((size_t)bh * NK_ + nj) * 2 + 1];
            }
            clo[tid] = lo;
            chi[tid] = hi;
        }
        __syncthreads();

        // ---- S = (Qh + Ql) . K̂h  (2 mma per fragment) ----
        float s[8][4];
        #pragma unroll
        for (int nf = 0; nf < 8; nf++) {
            s[nf][0] = 0.f; s[nf][1] = 0.f; s[nf][2] = 0.f; s[nf][3] = 0.f;
        }
        for (int kk = 0; kk < 8; kk++) {
            #pragma unroll
            for (int nf = 0; nf < 8; nf++) {
                int nb = (nf * 8 + g) * FST_ + kk * 8;
                uint32_t bhv[2] = {KH[nb + tig], KH[nb + tig + 4]};
                MMA_TF32(s[nf], qh[kk], bhv);
                MMA_TF32(s[nf], ql[kk], bhv);
            }
        }

        if (qleaf) {
            #pragma unroll
            for (int nf = 0; nf < 8; nf++) {
                int gj = j0 + nf * 8 + 2 * tig;
                if (key_pad[b * TK_ + gj])     { s[nf][0] = -1e30f; s[nf][2] = -1e30f; }
                if (key_pad[b * TK_ + gj + 1]) { s[nf][1] = -1e30f; s[nf][3] = -1e30f; }
            }
        } else if (!nodetile) {
            #pragma unroll
            for (int nf = 0; nf < 8; nf++) {
                int gj = j0 + nf * 8 + 2 * tig;
                bool kp0 = (key_pad[b * TK_ + gj] != 0);
                bool kp1 = (key_pad[b * TK_ + gj + 1] != 0);
                if (!(gj >= qloL0 && gj <= qhi0 && !kp0))             s[nf][0] = -1e30f;
                if (!((gj + 1) >= qloL0 && (gj + 1) <= qhi0 && !kp1)) s[nf][1] = -1e30f;
                if (!(gj >= qloL1 && gj <= qhi1 && !kp0))             s[nf][2] = -1e30f;
                if (!((gj + 1) >= qloL1 && (gj + 1) <= qhi1 && !kp1)) s[nf][3] = -1e30f;
            }
        } else {
            int nq0 = r0 - TK_, nq1 = r1 - TK_;
            #pragma unroll
            for (int nf = 0; nf < 8; nf++) {
                int cj = nf * 8 + 2 * tig;
                int nj0 = j0 + cj - TK_;
                int lo20 = clo[cj],     hi20 = chi[cj];
                int lo21 = clo[cj + 1], hi21 = chi[cj + 1];
                if (!(nj0 <= nq0 && max(qlo0, lo20) <= min(qhi0, hi20)))     s[nf][0] = -1e30f;
                if (!(nj0 + 1 <= nq0 && max(qlo0, lo21) <= min(qhi0, hi21))) s[nf][1] = -1e30f;
                if (!(nj0 <= nq1 && max(qlo1, lo20) <= min(qhi1, hi20)))     s[nf][2] = -1e30f;
                if (!(nj0 + 1 <= nq1 && max(qlo1, lo21) <= min(qhi1, hi21))) s[nf][3] = -1e30f;
            }
        }

        float tm0 = -1e30f, tm1 = -1e30f;
        #pragma unroll
        for (int nf = 0; nf < 8; nf++) {
            tm0 = fmaxf(tm0, fmaxf(s[nf][0], s[nf][1]));
            tm1 = fmaxf(tm1, fmaxf(s[nf][2], s[nf][3]));
        }
        tm0 = fmaxf(tm0, __shfl_xor_sync(0xffffffffu, tm0, 1));
        tm0 = fmaxf(tm0, __shfl_xor_sync(0xffffffffu, tm0, 2));
        tm1 = fmaxf(tm1, __shfl_xor_sync(0xffffffffu, tm1, 1));
        tm1 = fmaxf(tm1, __shfl_xor_sync(0xffffffffu, tm1, 2));

        float mn0 = fmaxf(m0, tm0);
        float mn1 = fmaxf(m1, tm1);
        float a0 = __expf(m0 - mn0);
        float a1 = __expf(m1 - mn1);
        m0 = mn0; m1 = mn1;
        float sb0 = fmaxf(mn0, -1e20f);
        float sb1 = fmaxf(mn1, -1e20f);

        float rs0 = 0.f, rs1 = 0.f;
        #pragma unroll
        for (int nf = 0; nf < 8; nf++) {
            s[nf][0] = __expf(s[nf][0] - sb0);
            s[nf][1] = __expf(s[nf][1] - sb0);
            s[nf][2] = __expf(s[nf][2] - sb1);
            s[nf][3] = __expf(s[nf][3] - sb1);
            rs0 += s[nf][0] + s[nf][1];
            rs1 += s[nf][2] + s[nf][3];
        }
        rs0 += __shfl_xor_sync(0xffffffffu, rs0, 1);
        rs0 += __shfl_xor_sync(0xffffffffu, rs0, 2);
        rs1 += __shfl_xor_sync(0xffffffffu, rs1, 1);
        rs1 += __shfl_xor_sync(0xffffffffu, rs1, 2);
        lsum0 = lsum0 * a0 + rs0;
        lsum1 = lsum1 * a1 + rs1;
        #pragma unroll
        for (int nf = 0; nf < 8; nf++) {
            acc[nf][0] *= a0; acc[nf][1] *= a0;
            acc[nf][2] *= a1; acc[nf][3] *= a1;
        }

        #pragma unroll
        for (int nf = 0; nf < 8; nf++) {
            int bg  = (wrow + g) * FST_ + nf * 8 + 2 * tig;
            int bg8 = (wrow + 8 + g) * FST_ + nf * 8 + 2 * tig;
            uint32_t h0, l0, h1, l1;
            split_tf32(s[nf][0], h0, l0);
            split_tf32(s[nf][1], h1, l1);
            *reinterpret_cast<uint2*>(PH + bg) = make_uint2(h0, h1);
            *reinterpret_cast<uint2*>(PL + bg) = make_uint2(l0, l1);
            split_tf32(s[nf][2], h0, l0);
            split_tf32(s[nf][3], h1, l1);
            *reinterpret_cast<uint2*>(PH + bg8) = make_uint2(h0, h1);
            *reinterpret_cast<uint2*>(PL + bg8) = make_uint2(l0, l1);
        }
        __syncwarp();

        // ---- acc += (Ph + Pl) . V̂h  (2 mma per fragment) ----
        for (int kk = 0; kk < 8; kk++) {
            int base0 = (wrow + g) * FST_ + kk * 8;
            int base1 = (wrow + 8 + g) * FST_ + kk * 8;
            uint32_t ah[4] = {PH[base0 + tig], PH[base1 + tig],
                              PH[base0 + tig + 4], PH[base1 + tig + 4]};
            uint32_t al[4] = {PL[base0 + tig], PL[base1 + tig],
                              PL[base0 + tig + 4], PL[base1 + tig + 4]};
            #pragma unroll
            for (int nf = 0; nf < 8; nf++) {
                int vb0 = (kk * 8 + tig) * FST_ + nf * 8 + g;
                int vb1 = (kk * 8 + tig + 4) * FST_ + nf * 8 + g;
                uint32_t bhv[2] = {VH[vb0], VH[vb1]};
                MMA_TF32(acc[nf], ah, bhv);
                MMA_TF32(acc[nf], al, bhv);
            }
        }
    }

    float inv0 = 1.0f / lsum0;
    float inv1 = 1.0f / lsum1;
    #pragma unroll
    for (int nf = 0; nf < 8; nf++) {
        int d0 = nf * 8 + 2 * tig;
        if (r0 < L_) {
            float2 v = make_float2(acc[nf][0] * inv0, acc[nf][1] * inv0);
            *reinterpret_cast<float2*>(g_ao + ((size_t)(b * L_ + r0)) * D_ + h * HD_ + d0) = v;
        }
        if (r1 < L_) {
            float2 v = make_float2(acc[nf][2] * inv1, acc[nf][3] * inv1);
            *reinterpret_cast<float2*>(g_ao + ((size_t)(b * L_ + r1)) * D_ + h * HD_ + d0) = v;
        }
    }
}

// ---------------------------------------------------------------------------
extern "C" void kernel_launch(void* const* d_in, const int* in_sizes, int n_in,
                              void* d_out, int out_size)
{
    const float* leaves = (const float*)d_in[0];
    const float* nodes  = (const float*)d_in[1];
    const float* Wq     = (const float*)d_in[2];
    const float* Wk     = (const float*)d_in[3];
    const float* Wv     = (const float*)d_in[4];
    const float* Wo     = (const float*)d_in[5];
    const float* bq     = (const float*)d_in[6];
    const float* bk     = (const float*)d_in[7];
    const float* bv     = (const float*)d_in[8];
    const float* bo     = (const float*)d_in[9];
    const int*   node_indices = (const int*)d_in[10];
    const unsigned char* key_pad  = (const unsigned char*)d_in[11];
    const unsigned char* node_pad = (const unsigned char*)d_in[12];
    float* out = (float*)d_out;

    static int smem_set = 0;
    if (!smem_set) {
        cudaFuncSetAttribute(flash_mma_kernel,
                             cudaFuncAttributeMaxDynamicSharedMemorySize,
                             FLASH_SMEM);
        cudaFuncSetAttribute(qkv_mma_kernel,
                             cudaFuncAttributeMaxDynamicSharedMemorySize,
                             GEMM_SMEM_BYTES);
        cudaFuncSetAttribute(oproj_mma_kernel,
                             cudaFuncAttributeMaxDynamicSharedMemorySize,
                             GEMM_SMEM_BYTES);
        smem_set = 1;
    }

    qkv_mma_kernel<<<dim3(8, 32, 3), 256, GEMM_SMEM_BYTES>>>(
        leaves, nodes, Wq, Wk, Wv, bq, bk, bv);
    flash_mma_kernel<<<dim3(32, 16), 128, FLASH_SMEM>>>(node_indices, key_pad, node_pad);
    oproj_mma_kernel<<<dim3(8, 32), 256, GEMM_SMEM_BYTES>>>(Wo, bo, out);
}